// round 8
// baseline (speedup 1.0000x reference)
#include <cuda_runtime.h>
#include <cuda_bf16.h>
#include <cstdint>
#include <math.h>

#define SQ   2048
#define HID  768
#define BB   2
#define NH   12
#define DH   64
#define RR   5
#define BN   24

// ---------------- device scratch ----------------
__device__ float g_v   [(size_t)BN * SQ * DH];
__device__ __nv_bfloat16 g_xh[(size_t)BB * SQ * HID];
__device__ __nv_bfloat16 g_xl[(size_t)BB * SQ * HID];
__device__ __nv_bfloat16 g_wh[(size_t)3 * HID * HID];
__device__ __nv_bfloat16 g_wl[(size_t)3 * HID * HID];
__device__ __nv_bfloat16 g_qh[(size_t)6 * BN * SQ * DH];   // slot 0..5 hi
__device__ __nv_bfloat16 g_ql[(size_t)BN * SQ * DH];       // slot 0 lo only
__device__ __nv_bfloat16 g_kh[(size_t)BN * SQ * DH];
__device__ __nv_bfloat16 g_kl[(size_t)BN * SQ * DH];
__device__ __nv_bfloat16 g_vth[(size_t)BN * DH * SQ];      // V^T [bn][d][s] hi
__device__ __nv_bfloat16 g_vtl[(size_t)BN * DH * SQ];      // V^T [bn][d][s] lo
__device__ unsigned g_adjbits[(size_t)RR * BB * (SQ / 32) * SQ];

// ================= helpers =================
__device__ __forceinline__ uint32_t smem_to_u32(const void* p) {
    uint32_t a;
    asm("{ .reg .u64 t; cvta.to.shared.u64 t, %1; cvt.u32.u64 %0, t; }" : "=r"(a) : "l"(p));
    return a;
}
__device__ __forceinline__ unsigned pack2(__nv_bfloat16 a, __nv_bfloat16 b) {
    __nv_bfloat162 t; t.x = a; t.y = b;
    return *reinterpret_cast<unsigned*>(&t);
}
__device__ __forceinline__ void ldsm_x4(uint32_t* r, uint32_t addr) {
    asm volatile("ldmatrix.sync.aligned.m8n8.x4.shared.b16 {%0,%1,%2,%3}, [%4];"
        : "=r"(r[0]), "=r"(r[1]), "=r"(r[2]), "=r"(r[3]) : "r"(addr));
}
__device__ __forceinline__ void ldsm_x2(uint32_t* r, uint32_t addr) {
    asm volatile("ldmatrix.sync.aligned.m8n8.x2.shared.b16 {%0,%1}, [%2];"
        : "=r"(r[0]), "=r"(r[1]) : "r"(addr));
}
__device__ __forceinline__ void mma16816(float* d, const uint32_t* a, const uint32_t* b) {
    asm volatile(
        "mma.sync.aligned.m16n8k16.row.col.f32.bf16.bf16.f32 "
        "{%0,%1,%2,%3}, {%4,%5,%6,%7}, {%8,%9}, {%0,%1,%2,%3};"
        : "+f"(d[0]), "+f"(d[1]), "+f"(d[2]), "+f"(d[3])
        : "r"(a[0]), "r"(a[1]), "r"(a[2]), "r"(a[3]), "r"(b[0]), "r"(b[1]));
}
__device__ __forceinline__ unsigned split_hi(float x, float y, float& lx, float& ly) {
    __nv_bfloat16 hx = __float2bfloat16(x), hy = __float2bfloat16(y);
    lx = x - __bfloat162float(hx);
    ly = y - __bfloat162float(hy);
    return pack2(hx, hy);
}
#define SWZ8(row, ch)   (((row) * 128) + ((((ch) ^ ((row) & 7))) << 4))

// ============ conv X -> bf16 hi/lo ============
__global__ __launch_bounds__(256) void convx_kernel(const float* __restrict__ X)
{
    int c = blockIdx.x * 256 + threadIdx.x;
    float4 v = ((const float4*)X)[c];
    float lx, ly, lz, lw;
    uint2 h, l;
    h.x = split_hi(v.x, v.y, lx, ly);
    h.y = split_hi(v.z, v.w, lz, lw);
    l.x = pack2(__float2bfloat16(lx), __float2bfloat16(ly));
    l.y = pack2(__float2bfloat16(lz), __float2bfloat16(lw));
    ((uint2*)g_xh)[c] = h;
    ((uint2*)g_xl)[c] = l;
}

// ============ conv W (q,k,v) -> bf16 hi/lo ============
__global__ __launch_bounds__(256) void convw_kernel(
    const float* __restrict__ Wq, const float* __restrict__ Wk, const float* __restrict__ Wv)
{
    const int per = HID * HID / 4;
    int c = blockIdx.x * 256 + threadIdx.x;
    int z = c / per;
    const float* W = (z == 0) ? Wq : (z == 1) ? Wk : Wv;
    float4 v = ((const float4*)W)[c - z * per];
    float lx, ly, lz, lw;
    uint2 h, l;
    h.x = split_hi(v.x, v.y, lx, ly);
    h.y = split_hi(v.z, v.w, lz, lw);
    l.x = pack2(__float2bfloat16(lx), __float2bfloat16(ly));
    l.y = pack2(__float2bfloat16(lz), __float2bfloat16(lw));
    ((uint2*)g_wh)[c] = h;
    ((uint2*)g_wl)[c] = l;
}

// ============ proj via HMMA: out = X @ W^T + b ============
#define PJ_XH 0
#define PJ_XL 16384
#define PJ_WH 32768
#define PJ_WL 40960
#define PJ_SMEM 49152

__global__ __launch_bounds__(256) void proj_mma_kernel(
    const float* __restrict__ bq, const float* __restrict__ bk, const float* __restrict__ bv)
{
    extern __shared__ char smem[];
    const uint32_t sbase = smem_to_u32(smem);
    const int otile = blockIdx.x, mtile = blockIdx.y, z = blockIdx.z;
    const float* bias = (z == 0) ? bq : (z == 1) ? bk : bv;
    const int tid = threadIdx.x, wid = tid >> 5, lane = tid & 31;
    const int m0 = wid * 16;
    const int rowA = m0 + (lane & 15);
    const int selA = lane >> 4;
    const int rowB8 = lane & 7;
    const int selB = (lane >> 3) & 1;
    const int c2 = 2 * (lane & 3);

    float fin[32];
#pragma unroll
    for (int e = 0; e < 32; e++) fin[e] = 0.f;

    for (int kc = 0; kc < HID / 64; kc++) {
        __syncthreads();
#pragma unroll
        for (int c = 0; c < 8; c++) {
            int idx = tid + 256 * c;
            int half = idx >> 10;
            int rem = idx & 1023;
            int row = rem >> 3, ch = rem & 7;
            const __nv_bfloat16* src = (half ? g_xl : g_xh) +
                (size_t)(mtile * 128 + row) * HID + kc * 64 + ch * 8;
            *(uint4*)(smem + (half ? PJ_XL : PJ_XH) + SWZ8(row, ch)) = *(const uint4*)src;
        }
#pragma unroll
        for (int c = 0; c < 4; c++) {
            int idx = tid + 256 * c;
            int half = idx >> 9;
            int rem = idx & 511;
            int row = rem >> 3, ch = rem & 7;
            const __nv_bfloat16* src = (half ? g_wl : g_wh) +
                ((size_t)z * HID + otile * 64 + row) * HID + kc * 64 + ch * 8;
            *(uint4*)(smem + (half ? PJ_WL : PJ_WH) + SWZ8(row, ch)) = *(const uint4*)src;
        }
        __syncthreads();

#pragma unroll
        for (int ks = 0; ks < 4; ks++) {
            uint32_t Ah[4], Al[4];
            ldsm_x4(Ah, sbase + PJ_XH + SWZ8(rowA, ks * 2 + selA));
            ldsm_x4(Al, sbase + PJ_XL + SWZ8(rowA, ks * 2 + selA));
#pragma unroll
            for (int nf = 0; nf < 8; nf++) {
                uint32_t Bh[2], Bl[2];
                ldsm_x2(Bh, sbase + PJ_WH + SWZ8(nf * 8 + rowB8, ks * 2 + selB));
                ldsm_x2(Bl, sbase + PJ_WL + SWZ8(nf * 8 + rowB8, ks * 2 + selB));
                mma16816(fin + nf * 4, Ah, Bh);
                mma16816(fin + nf * 4, Ah, Bl);
                mma16816(fin + nf * 4, Al, Bh);
            }
        }
    }

    const int ma = mtile * 128 + m0 + (lane >> 2);
    const int b = ma >> 11;
    const int sa = ma & (SQ - 1), sb = sa + 8;
    const int bn = b * NH + otile;
#pragma unroll
    for (int nf = 0; nf < 8; nf++) {
        int col = nf * 8 + c2;
        float bsx = bias[otile * 64 + col], bsy = bias[otile * 64 + col + 1];
        float a0 = fin[nf * 4 + 0] + bsx, a1 = fin[nf * 4 + 1] + bsy;
        float b0 = fin[nf * 4 + 2] + bsx, b1 = fin[nf * 4 + 3] + bsy;
        size_t offa = ((size_t)bn * SQ + sa) * DH + col;
        size_t offb = ((size_t)bn * SQ + sb) * DH + col;
        if (z == 2) {
            *(float2*)&g_v[offa] = make_float2(a0, a1);
            *(float2*)&g_v[offb] = make_float2(b0, b1);
        } else {
            __nv_bfloat16* dh = (z == 0) ? g_qh : g_kh;
            __nv_bfloat16* dl = (z == 0) ? g_ql : g_kl;
            float l0, l1;
            unsigned h;
            h = split_hi(a0, a1, l0, l1);
            *(unsigned*)&dh[offa] = h;
            *(unsigned*)&dl[offa] = pack2(__float2bfloat16(l0), __float2bfloat16(l1));
            h = split_hi(b0, b1, l0, l1);
            *(unsigned*)&dh[offb] = h;
            *(unsigned*)&dl[offb] = pack2(__float2bfloat16(l0), __float2bfloat16(l1));
        }
    }
}

// ============ qb via HMMA: q'_r = q @ bili[r,n] -> slot 1+r (hi only) ============
#define QB_QH 0
#define QB_QL 16384
#define QB_BH 32768
#define QB_BL 40960
#define QB_SMEM 49152

__global__ __launch_bounds__(256) void qb_mma_kernel(const float* __restrict__ bili)
{
    extern __shared__ char smem[];
    const uint32_t sbase = smem_to_u32(smem);
    const int it = blockIdx.x, bn = blockIdx.y, r = blockIdx.z;
    const int n = bn % NH;
    const int tid = threadIdx.x, wid = tid >> 5, lane = tid & 31;
    const int m0 = wid * 16;
    const int rowA = m0 + (lane & 15);
    const int selA = lane >> 4;
    const int rowB8 = lane & 7;
    const int selB = (lane >> 3) & 1;
    const int c2 = 2 * (lane & 3);

#pragma unroll
    for (int c = 0; c < 8; c++) {
        int idx = tid + 256 * c;
        int half = idx >> 10;
        int rem = idx & 1023;
        int row = rem >> 3, ch = rem & 7;
        const __nv_bfloat16* src = (half ? g_ql : g_qh) +
            ((size_t)bn * SQ + it * 128 + row) * DH + ch * 8;
        *(uint4*)(smem + (half ? QB_QL : QB_QH) + SWZ8(row, ch)) = *(const uint4*)src;
    }
    const float* bb = bili + ((size_t)r * NH + n) * DH * DH;
#pragma unroll
    for (int c = 0; c < 16; c++) {
        int id = tid + 256 * c;
        int p = id >> 6, t = id & 63;
        float v = bb[p * 64 + t];
        __nv_bfloat16 hv = __float2bfloat16(v);
        float lo = v - __bfloat162float(hv);
        uint32_t byteoff = SWZ8(t, p >> 3) + (p & 7) * 2;
        *(__nv_bfloat16*)(smem + QB_BH + byteoff) = hv;
        *(__nv_bfloat16*)(smem + QB_BL + byteoff) = __float2bfloat16(lo);
    }
    __syncthreads();

    float fin[32];
#pragma unroll
    for (int e = 0; e < 32; e++) fin[e] = 0.f;

#pragma unroll
    for (int ks = 0; ks < 4; ks++) {
        uint32_t Ah[4], Al[4];
        ldsm_x4(Ah, sbase + QB_QH + SWZ8(rowA, ks * 2 + selA));
        ldsm_x4(Al, sbase + QB_QL + SWZ8(rowA, ks * 2 + selA));
#pragma unroll
        for (int nf = 0; nf < 8; nf++) {
            uint32_t Bh[2], Bl[2];
            ldsm_x2(Bh, sbase + QB_BH + SWZ8(nf * 8 + rowB8, ks * 2 + selB));
            ldsm_x2(Bl, sbase + QB_BL + SWZ8(nf * 8 + rowB8, ks * 2 + selB));
            mma16816(fin + nf * 4, Ah, Bh);
            mma16816(fin + nf * 4, Ah, Bl);
            mma16816(fin + nf * 4, Al, Bh);
        }
    }

    const int slot = 1 + r;
    const int ia = it * 128 + m0 + (lane >> 2);
    const int ib = ia + 8;
#pragma unroll
    for (int nf = 0; nf < 8; nf++) {
        int col = nf * 8 + c2;
        size_t offa = (((size_t)slot * BN + bn) * SQ + ia) * DH + col;
        size_t offb = (((size_t)slot * BN + bn) * SQ + ib) * DH + col;
        *(unsigned*)&g_qh[offa] = pack2(__float2bfloat16(fin[nf * 4 + 0]), __float2bfloat16(fin[nf * 4 + 1]));
        *(unsigned*)&g_qh[offb] = pack2(__float2bfloat16(fin[nf * 4 + 2]), __float2bfloat16(fin[nf * 4 + 3]));
    }
}

// ============ transpose+convert V -> g_vth/g_vtl [bn][d][s] ============
__global__ __launch_bounds__(256) void vt_kernel()
{
    const int st = blockIdx.x, bn = blockIdx.y;
    __shared__ float tile[64][65];
    const int t = threadIdx.x;
#pragma unroll
    for (int c = 0; c < 4; c++) {
        int id = t + 256 * c, row = id >> 4, c4 = (id & 15) << 2;
        float4 v = *(const float4*)&g_v[((size_t)bn * SQ + st * 64 + row) * DH + c4];
        tile[row][c4 + 0] = v.x; tile[row][c4 + 1] = v.y;
        tile[row][c4 + 2] = v.z; tile[row][c4 + 3] = v.w;
    }
    __syncthreads();
#pragma unroll
    for (int c = 0; c < 4; c++) {
        int id = t + 256 * c, d = id >> 4, s4 = (id & 15) << 2;
        float f0 = tile[s4 + 0][d], f1 = tile[s4 + 1][d];
        float f2 = tile[s4 + 2][d], f3 = tile[s4 + 3][d];
        float l0, l1, l2, l3;
        uint2 hv, lv;
        hv.x = split_hi(f0, f1, l0, l1);
        hv.y = split_hi(f2, f3, l2, l3);
        lv.x = pack2(__float2bfloat16(l0), __float2bfloat16(l1));
        lv.y = pack2(__float2bfloat16(l2), __float2bfloat16(l3));
        size_t off = ((size_t)bn * DH + d) * SQ + st * 64 + s4;
        *(uint2*)&g_vth[off] = hv;
        *(uint2*)&g_vtl[off] = lv;
    }
}

// ============ pack adj -> bitmask [r][b][jword][i] ============
__global__ __launch_bounds__(256) void pack_kernel(const float* __restrict__ adj)
{
    const int jw = blockIdx.x, b = blockIdx.y, r = blockIdx.z;
#pragma unroll
    for (int ii = 0; ii < 8; ii++) {
        int i = threadIdx.x + 256 * ii;
        const float* src = adj + (((size_t)(r * BB + b)) * SQ + i) * SQ + jw * 32;
        unsigned bits = 0;
#pragma unroll
        for (int e8 = 0; e8 < 8; e8++) {
            float4 v = *(const float4*)(src + e8 * 4);
            bits |= (unsigned)(v.x != 0.f) << (e8 * 4 + 0);
            bits |= (unsigned)(v.y != 0.f) << (e8 * 4 + 1);
            bits |= (unsigned)(v.z != 0.f) << (e8 * 4 + 2);
            bits |= (unsigned)(v.w != 0.f) << (e8 * 4 + 3);
        }
        g_adjbits[((size_t)(r * BB + b) * 64 + jw) * SQ + i] = bits;
    }
}

// ============ fused flash (score + softmax + ctx) ============
// grid (NH, SQ/64, BB), block 128 (4 warps x 16 rows). 2 CTAs/SM.
#define FQ0H 0
#define FQ0L 8192
#define FQS(s)    (((s) + 1) * 8192)        // s in 1..5
#define FKT(half) (57344 + (half) * 8192)
#define FVT(half) (73728 + (half) * 8192)
#define FL_SMEM   90112

__global__ __launch_bounds__(128) void flash_kernel(
    const float* __restrict__ absb, const float* __restrict__ mask,
    float* __restrict__ out)
{
    extern __shared__ char smem[];
    const uint32_t sbase = smem_to_u32(smem);
    const int n = blockIdx.x, it = blockIdx.y, b = blockIdx.z;
    const int bn = b * NH + n;
    const int i0 = it * 64;
    const int tid = threadIdx.x, wid = tid >> 5, lane = tid & 31;
    const int m0 = wid * 16;

    // ---- load 7 Q tiles (64x64 bf16, swizzled): slot0 h+l, slots1-5 hi ----
#pragma unroll
    for (int c = 0; c < 28; c++) {
        int idx = tid + 128 * c;
        int tile = idx >> 9;
        int rem = idx & 511;
        int row = rem >> 3, ch = rem & 7;
        int slot = (tile <= 1) ? 0 : (tile - 1);
        const __nv_bfloat16* base = (tile == 1) ? g_ql : g_qh;
        const __nv_bfloat16* src = base +
            (((size_t)slot * BN + bn) * SQ + i0 + row) * DH + ch * 8;
        *(uint4*)(smem + tile * 8192 + SWZ8(row, ch)) = *(const uint4*)src;
    }
    __syncthreads();

    const int rowA = m0 + (lane & 15);
    const int selA = lane >> 4;
    const int rowB8 = lane & 7;
    const int selB = (lane >> 3) & 1;
    const int ksB  = lane >> 4;          // +0/+1 chunk for x4 B loads
    const int c2 = 2 * (lane & 3);
    const int ia = i0 + m0 + (lane >> 2);
    const int ib = ia + 8;

    // ---- hoist ALL Q A-fragments into registers (jt-invariant) ----
    uint32_t A0h[4][4], A0l[4][4], As[5][4][4];
#pragma unroll
    for (int ks = 0; ks < 4; ks++) {
        ldsm_x4(A0h[ks], sbase + FQ0H + SWZ8(rowA, ks * 2 + selA));
        ldsm_x4(A0l[ks], sbase + FQ0L + SWZ8(rowA, ks * 2 + selA));
#pragma unroll
        for (int s = 0; s < 5; s++)
            ldsm_x4(As[s][ks], sbase + FQS(s + 1) + SWZ8(rowA, ks * 2 + selA));
    }

    float ab[RR];
#pragma unroll
    for (int r = 0; r < RR; r++) ab[r] = absb[r * NH + n];
    const float* maskb = mask + b * SQ;

    float O[32];
#pragma unroll
    for (int e = 0; e < 32; e++) O[e] = 0.f;
    float mr[2] = {-1e30f, -1e30f};
    float lr[2] = {0.f, 0.f};

    for (int jt = 0; jt < 32; jt++) {
        __syncthreads();
        // ---- load K hi/lo (64x64) and Vt hi/lo (64d x 64j) ----
#pragma unroll
        for (int c = 0; c < 16; c++) {
            int idx = tid + 128 * c;
            int seg = idx >> 9;
            int rem = idx & 511;
            int row = rem >> 3, ch = rem & 7;
            const __nv_bfloat16* src;
            uint32_t dstoff;
            if (seg < 2) {
                src = (seg ? g_kl : g_kh) + ((size_t)bn * SQ + jt * 64 + row) * DH + ch * 8;
                dstoff = FKT(seg);
            } else {
                src = ((seg == 3) ? g_vtl : g_vth) + ((size_t)bn * DH + row) * SQ + jt * 64 + ch * 8;
                dstoff = FVT(seg - 2);
            }
            *(uint4*)(smem + dstoff + SWZ8(row, ch)) = *(const uint4*)src;
        }
        __syncthreads();

        // ---- QK: full 64 cols into fin[32] ----
        float fin[32];
#pragma unroll
        for (int jh = 0; jh < 2; jh++) {
            unsigned aw1[RR], aw2[RR];
            const int jw = jt * 2 + jh;
#pragma unroll
            for (int r = 0; r < RR; r++) {
                aw1[r] = g_adjbits[((size_t)(r * BB + b) * 64 + jw) * SQ + ia];
                aw2[r] = g_adjbits[((size_t)(r * BB + b) * 64 + jw) * SQ + ib];
            }
#pragma unroll
            for (int nf = 0; nf < 4; nf++) {
                float acc0[4] = {};
                float tmp[5][4] = {};
#pragma unroll
                for (int ksp = 0; ksp < 2; ksp++) {
                    uint32_t Bh[4], Bl[4];
                    uint32_t baddr = SWZ8(jh * 32 + nf * 8 + rowB8, (2 * ksp + ksB) * 2 + selB);
                    ldsm_x4(Bh, sbase + FKT(0) + baddr);
                    ldsm_x4(Bl, sbase + FKT(1) + baddr);
                    mma16816(acc0, A0h[2 * ksp + 0], Bh + 0);
                    mma16816(acc0, A0h[2 * ksp + 0], Bl + 0);
                    mma16816(acc0, A0l[2 * ksp + 0], Bh + 0);
                    mma16816(acc0, A0h[2 * ksp + 1], Bh + 2);
                    mma16816(acc0, A0h[2 * ksp + 1], Bl + 2);
                    mma16816(acc0, A0l[2 * ksp + 1], Bh + 2);
#pragma unroll
                    for (int s = 0; s < 5; s++) {
                        mma16816(tmp[s], As[s][2 * ksp + 0], Bh + 0);
                        mma16816(tmp[s], As[s][2 * ksp + 1], Bh + 2);
                    }
                }
                const int sh = nf * 8 + c2;
                float f0 = acc0[0], f1 = acc0[1], f2 = acc0[2], f3 = acc0[3];
#pragma unroll
                for (int r = 0; r < RR; r++) {
                    const float abr = ab[r];
                    if ((aw1[r] >> sh) & 1)       f0 += tmp[r][0] + abr;
                    if ((aw1[r] >> (sh + 1)) & 1) f1 += tmp[r][1] + abr;
                    if ((aw2[r] >> sh) & 1)       f2 += tmp[r][2] + abr;
                    if ((aw2[r] >> (sh + 1)) & 1) f3 += tmp[r][3] + abr;
                }
                fin[jh * 16 + nf * 4 + 0] = f0;
                fin[jh * 16 + nf * 4 + 1] = f1;
                fin[jh * 16 + nf * 4 + 2] = f2;
                fin[jh * 16 + nf * 4 + 3] = f3;
            }
        }

        // ---- scale + mask (one pass over 64 cols) ----
#pragma unroll
        for (int q = 0; q < 8; q++) {
            int jh = q >> 2, nf = q & 3;
            float2 mk = __ldg((const float2*)&maskb[jt * 64 + jh * 32 + nf * 8 + c2]);
            fin[q * 4 + 0] = fin[q * 4 + 0] * 0.125f + mk.x;
            fin[q * 4 + 1] = fin[q * 4 + 1] * 0.125f + mk.y;
            fin[q * 4 + 2] = fin[q * 4 + 2] * 0.125f + mk.x;
            fin[q * 4 + 3] = fin[q * 4 + 3] * 0.125f + mk.y;
        }

        // ---- single online-softmax update over 64 cols ----
        float mxa = -1e30f, mxb = -1e30f;
#pragma unroll
        for (int q = 0; q < 8; q++) {
            mxa = fmaxf(mxa, fmaxf(fin[q * 4 + 0], fin[q * 4 + 1]));
            mxb = fmaxf(mxb, fmaxf(fin[q * 4 + 2], fin[q * 4 + 3]));
        }
        mxa = fmaxf(mxa, __shfl_xor_sync(0xffffffffu, mxa, 1));
        mxa = fmaxf(mxa, __shfl_xor_sync(0xffffffffu, mxa, 2));
        mxb = fmaxf(mxb, __shfl_xor_sync(0xffffffffu, mxb, 1));
        mxb = fmaxf(mxb, __shfl_xor_sync(0xffffffffu, mxb, 2));
        float mna = fmaxf(mr[0], mxa), mnb = fmaxf(mr[1], mxb);
        float ala = __expf(mr[0] - mna), alb = __expf(mr[1] - mnb);
        mr[0] = mna; mr[1] = mnb;

        float sa = 0.f, sb = 0.f;
#pragma unroll
        for (int q = 0; q < 8; q++) {
            fin[q * 4 + 0] = __expf(fin[q * 4 + 0] - mna);
            fin[q * 4 + 1] = __expf(fin[q * 4 + 1] - mna);
            fin[q * 4 + 2] = __expf(fin[q * 4 + 2] - mnb);
            fin[q * 4 + 3] = __expf(fin[q * 4 + 3] - mnb);
            sa += fin[q * 4 + 0] + fin[q * 4 + 1];
            sb += fin[q * 4 + 2] + fin[q * 4 + 3];
        }
        sa += __shfl_xor_sync(0xffffffffu, sa, 1);
        sa += __shfl_xor_sync(0xffffffffu, sa, 2);
        sb += __shfl_xor_sync(0xffffffffu, sb, 1);
        sb += __shfl_xor_sync(0xffffffffu, sb, 2);
        lr[0] = lr[0] * ala + sa;
        lr[1] = lr[1] * alb + sb;

#pragma unroll
        for (int dn = 0; dn < 8; dn++) {
            O[dn * 4 + 0] *= ala; O[dn * 4 + 1] *= ala;
            O[dn * 4 + 2] *= alb; O[dn * 4 + 3] *= alb;
        }

        // ---- pack P (K=64 -> 4 k-chunks) ----
        uint32_t Ph[4][4], Pl[4][4];
#pragma unroll
        for (int jk = 0; jk < 4; jk++) {
            int jh = jk >> 1, jj = jk & 1;
            int b0 = jh * 16 + (2 * jj) * 4;
            int b1 = jh * 16 + (2 * jj + 1) * 4;
            float l0, l1;
            Ph[jk][0] = split_hi(fin[b0 + 0], fin[b0 + 1], l0, l1);
            Pl[jk][0] = pack2(__float2bfloat16(l0), __float2bfloat16(l1));
            Ph[jk][1] = split_hi(fin[b0 + 2], fin[b0 + 3], l0, l1);
            Pl[jk][1] = pack2(__float2bfloat16(l0), __float2bfloat16(l1));
            Ph[jk][2] = split_hi(fin[b1 + 0], fin[b1 + 1], l0, l1);
            Pl[jk][2] = pack2(__float2bfloat16(l0), __float2bfloat16(l1));
            Ph[jk][3] = split_hi(fin[b1 + 2], fin[b1 + 3], l0, l1);
            Pl[jk][3] = pack2(__float2bfloat16(l0), __float2bfloat16(l1));
        }

        // ---- P @ V: x4 B loads (two d-fragments per ldsm) ----
#pragma unroll
        for (int jk = 0; jk < 4; jk++) {
#pragma unroll
            for (int dnp = 0; dnp < 4; dnp++) {
                uint32_t BVh[4], BVl[4];
                uint32_t vaddr = SWZ8((2 * dnp + ksB) * 8 + rowB8, jk * 2 + selB);
                ldsm_x4(BVh, sbase + FVT(0) + vaddr);
                ldsm_x4(BVl, sbase + FVT(1) + vaddr);
                mma16816(O + (2 * dnp + 0) * 4, Ph[jk], BVh + 0);
                mma16816(O + (2 * dnp + 0) * 4, Ph[jk], BVl + 0);
                mma16816(O + (2 * dnp + 0) * 4, Pl[jk], BVh + 0);
                mma16816(O + (2 * dnp + 1) * 4, Ph[jk], BVh + 2);
                mma16816(O + (2 * dnp + 1) * 4, Ph[jk], BVl + 2);
                mma16816(O + (2 * dnp + 1) * 4, Pl[jk], BVh + 2);
            }
        }
    }

    const float inva = 1.0f / lr[0], invb = 1.0f / lr[1];
#pragma unroll
    for (int dn = 0; dn < 8; dn++) {
        int d = dn * 8 + c2;
        float2 oa, ob;
        oa.x = O[dn * 4 + 0] * inva; oa.y = O[dn * 4 + 1] * inva;
        ob.x = O[dn * 4 + 2] * invb; ob.y = O[dn * 4 + 3] * invb;
        *(float2*)&out[((size_t)b * SQ + ia) * HID + n * 64 + d] = oa;
        *(float2*)&out[((size_t)b * SQ + ib) * HID + n * 64 + d] = ob;
    }
}

// =================================================================
extern "C" void kernel_launch(void* const* d_in, const int* in_sizes, int n_in,
                              void* d_out, int out_size)
{
    const float* hidden = (const float*)d_in[0];
    const float* mask   = (const float*)d_in[1];
    const float* adj    = (const float*)d_in[2];
    const float* Wq     = (const float*)d_in[3];
    const float* bq     = (const float*)d_in[4];
    const float* Wk     = (const float*)d_in[5];
    const float* bk     = (const float*)d_in[6];
    const float* Wv     = (const float*)d_in[7];
    const float* bv     = (const float*)d_in[8];
    const float* bili   = (const float*)d_in[9];
    const float* absb   = (const float*)d_in[10];
    float* out = (float*)d_out;
    (void)in_sizes; (void)n_in; (void)out_size;

    cudaFuncSetAttribute(proj_mma_kernel, cudaFuncAttributeMaxDynamicSharedMemorySize, PJ_SMEM);
    cudaFuncSetAttribute(qb_mma_kernel, cudaFuncAttributeMaxDynamicSharedMemorySize, QB_SMEM);
    cudaFuncSetAttribute(flash_kernel, cudaFuncAttributeMaxDynamicSharedMemorySize, FL_SMEM);

    convx_kernel<<<BB * SQ * HID / 4 / 256, 256>>>(hidden);
    convw_kernel<<<3 * HID * HID / 4 / 256, 256>>>(Wq, Wk, Wv);
    proj_mma_kernel<<<dim3(HID / 64, BB * SQ / 128, 3), 256, PJ_SMEM>>>(bq, bk, bv);
    qb_mma_kernel<<<dim3(SQ / 128, BN, RR), 256, QB_SMEM>>>(bili);
    vt_kernel<<<dim3(SQ / 64, BN), 256>>>();
    pack_kernel<<<dim3(SQ / 32, BB, RR), 256>>>(adj);
    flash_kernel<<<dim3(NH, SQ / 64, BB), 128, FL_SMEM>>>(absb, mask, out);
}

// round 9
// speedup vs baseline: 1.0035x; 1.0035x over previous
#include <cuda_runtime.h>
#include <cuda_bf16.h>
#include <cstdint>
#include <math.h>

#define SQ   2048
#define HID  768
#define BB   2
#define NH   12
#define DH   64
#define RR   5
#define BN   24

// ---------------- device scratch ----------------
__device__ float g_v   [(size_t)BN * SQ * DH];
__device__ __nv_bfloat16 g_xh[(size_t)BB * SQ * HID];
__device__ __nv_bfloat16 g_xl[(size_t)BB * SQ * HID];
__device__ __nv_bfloat16 g_wh[(size_t)3 * HID * HID];
__device__ __nv_bfloat16 g_wl[(size_t)3 * HID * HID];
__device__ __nv_bfloat16 g_qh[(size_t)6 * BN * SQ * DH];   // slot 0..5 hi
__device__ __nv_bfloat16 g_ql[(size_t)BN * SQ * DH];       // slot 0 lo only
__device__ __nv_bfloat16 g_kh[(size_t)BN * SQ * DH];
__device__ __nv_bfloat16 g_kl[(size_t)BN * SQ * DH];
__device__ __nv_bfloat16 g_vth[(size_t)BN * DH * SQ];      // V^T [bn][d][s] hi
__device__ __nv_bfloat16 g_vtl[(size_t)BN * DH * SQ];      // V^T [bn][d][s] lo
__device__ unsigned g_adjbits[(size_t)RR * BB * (SQ / 32) * SQ];

// ================= helpers =================
__device__ __forceinline__ uint32_t smem_to_u32(const void* p) {
    uint32_t a;
    asm("{ .reg .u64 t; cvta.to.shared.u64 t, %1; cvt.u32.u64 %0, t; }" : "=r"(a) : "l"(p));
    return a;
}
__device__ __forceinline__ unsigned pack2(__nv_bfloat16 a, __nv_bfloat16 b) {
    __nv_bfloat162 t; t.x = a; t.y = b;
    return *reinterpret_cast<unsigned*>(&t);
}
__device__ __forceinline__ void ldsm_x4(uint32_t* r, uint32_t addr) {
    asm volatile("ldmatrix.sync.aligned.m8n8.x4.shared.b16 {%0,%1,%2,%3}, [%4];"
        : "=r"(r[0]), "=r"(r[1]), "=r"(r[2]), "=r"(r[3]) : "r"(addr));
}
__device__ __forceinline__ void ldsm_x2(uint32_t* r, uint32_t addr) {
    asm volatile("ldmatrix.sync.aligned.m8n8.x2.shared.b16 {%0,%1}, [%2];"
        : "=r"(r[0]), "=r"(r[1]) : "r"(addr));
}
__device__ __forceinline__ void mma16816(float* d, const uint32_t* a, const uint32_t* b) {
    asm volatile(
        "mma.sync.aligned.m16n8k16.row.col.f32.bf16.bf16.f32 "
        "{%0,%1,%2,%3}, {%4,%5,%6,%7}, {%8,%9}, {%0,%1,%2,%3};"
        : "+f"(d[0]), "+f"(d[1]), "+f"(d[2]), "+f"(d[3])
        : "r"(a[0]), "r"(a[1]), "r"(a[2]), "r"(a[3]), "r"(b[0]), "r"(b[1]));
}
__device__ __forceinline__ unsigned split_hi(float x, float y, float& lx, float& ly) {
    __nv_bfloat16 hx = __float2bfloat16(x), hy = __float2bfloat16(y);
    lx = x - __bfloat162float(hx);
    ly = y - __bfloat162float(hy);
    return pack2(hx, hy);
}
#define SWZ8(row, ch)   (((row) * 128) + ((((ch) ^ ((row) & 7))) << 4))

// ============ conv X -> bf16 hi/lo ============
__global__ __launch_bounds__(256) void convx_kernel(const float* __restrict__ X)
{
    int c = blockIdx.x * 256 + threadIdx.x;
    float4 v = ((const float4*)X)[c];
    float lx, ly, lz, lw;
    uint2 h, l;
    h.x = split_hi(v.x, v.y, lx, ly);
    h.y = split_hi(v.z, v.w, lz, lw);
    l.x = pack2(__float2bfloat16(lx), __float2bfloat16(ly));
    l.y = pack2(__float2bfloat16(lz), __float2bfloat16(lw));
    ((uint2*)g_xh)[c] = h;
    ((uint2*)g_xl)[c] = l;
}

// ============ conv W (q,k,v) -> bf16 hi/lo ============
__global__ __launch_bounds__(256) void convw_kernel(
    const float* __restrict__ Wq, const float* __restrict__ Wk, const float* __restrict__ Wv)
{
    const int per = HID * HID / 4;
    int c = blockIdx.x * 256 + threadIdx.x;
    int z = c / per;
    const float* W = (z == 0) ? Wq : (z == 1) ? Wk : Wv;
    float4 v = ((const float4*)W)[c - z * per];
    float lx, ly, lz, lw;
    uint2 h, l;
    h.x = split_hi(v.x, v.y, lx, ly);
    h.y = split_hi(v.z, v.w, lz, lw);
    l.x = pack2(__float2bfloat16(lx), __float2bfloat16(ly));
    l.y = pack2(__float2bfloat16(lz), __float2bfloat16(lw));
    ((uint2*)g_wh)[c] = h;
    ((uint2*)g_wl)[c] = l;
}

// ============ proj via HMMA: out = X @ W^T + b ============
#define PJ_XH 0
#define PJ_XL 16384
#define PJ_WH 32768
#define PJ_WL 40960
#define PJ_SMEM 49152

__global__ __launch_bounds__(256) void proj_mma_kernel(
    const float* __restrict__ bq, const float* __restrict__ bk, const float* __restrict__ bv)
{
    extern __shared__ char smem[];
    const uint32_t sbase = smem_to_u32(smem);
    const int otile = blockIdx.x, mtile = blockIdx.y, z = blockIdx.z;
    const float* bias = (z == 0) ? bq : (z == 1) ? bk : bv;
    const int tid = threadIdx.x, wid = tid >> 5, lane = tid & 31;
    const int m0 = wid * 16;
    const int rowA = m0 + (lane & 15);
    const int selA = lane >> 4;
    const int rowB8 = lane & 7;
    const int selB = (lane >> 3) & 1;
    const int c2 = 2 * (lane & 3);

    float fin[32];
#pragma unroll
    for (int e = 0; e < 32; e++) fin[e] = 0.f;

    for (int kc = 0; kc < HID / 64; kc++) {
        __syncthreads();
#pragma unroll
        for (int c = 0; c < 8; c++) {
            int idx = tid + 256 * c;
            int half = idx >> 10;
            int rem = idx & 1023;
            int row = rem >> 3, ch = rem & 7;
            const __nv_bfloat16* src = (half ? g_xl : g_xh) +
                (size_t)(mtile * 128 + row) * HID + kc * 64 + ch * 8;
            *(uint4*)(smem + (half ? PJ_XL : PJ_XH) + SWZ8(row, ch)) = *(const uint4*)src;
        }
#pragma unroll
        for (int c = 0; c < 4; c++) {
            int idx = tid + 256 * c;
            int half = idx >> 9;
            int rem = idx & 511;
            int row = rem >> 3, ch = rem & 7;
            const __nv_bfloat16* src = (half ? g_wl : g_wh) +
                ((size_t)z * HID + otile * 64 + row) * HID + kc * 64 + ch * 8;
            *(uint4*)(smem + (half ? PJ_WL : PJ_WH) + SWZ8(row, ch)) = *(const uint4*)src;
        }
        __syncthreads();

#pragma unroll
        for (int ks = 0; ks < 4; ks++) {
            uint32_t Ah[4], Al[4];
            ldsm_x4(Ah, sbase + PJ_XH + SWZ8(rowA, ks * 2 + selA));
            ldsm_x4(Al, sbase + PJ_XL + SWZ8(rowA, ks * 2 + selA));
#pragma unroll
            for (int nf = 0; nf < 8; nf++) {
                uint32_t Bh[2], Bl[2];
                ldsm_x2(Bh, sbase + PJ_WH + SWZ8(nf * 8 + rowB8, ks * 2 + selB));
                ldsm_x2(Bl, sbase + PJ_WL + SWZ8(nf * 8 + rowB8, ks * 2 + selB));
                mma16816(fin + nf * 4, Ah, Bh);
                mma16816(fin + nf * 4, Ah, Bl);
                mma16816(fin + nf * 4, Al, Bh);
            }
        }
    }

    const int ma = mtile * 128 + m0 + (lane >> 2);
    const int b = ma >> 11;
    const int sa = ma & (SQ - 1), sb = sa + 8;
    const int bn = b * NH + otile;
#pragma unroll
    for (int nf = 0; nf < 8; nf++) {
        int col = nf * 8 + c2;
        float bsx = bias[otile * 64 + col], bsy = bias[otile * 64 + col + 1];
        float a0 = fin[nf * 4 + 0] + bsx, a1 = fin[nf * 4 + 1] + bsy;
        float b0 = fin[nf * 4 + 2] + bsx, b1 = fin[nf * 4 + 3] + bsy;
        size_t offa = ((size_t)bn * SQ + sa) * DH + col;
        size_t offb = ((size_t)bn * SQ + sb) * DH + col;
        if (z == 2) {
            *(float2*)&g_v[offa] = make_float2(a0, a1);
            *(float2*)&g_v[offb] = make_float2(b0, b1);
        } else {
            __nv_bfloat16* dh = (z == 0) ? g_qh : g_kh;
            __nv_bfloat16* dl = (z == 0) ? g_ql : g_kl;
            float l0, l1;
            unsigned h;
            h = split_hi(a0, a1, l0, l1);
            *(unsigned*)&dh[offa] = h;
            *(unsigned*)&dl[offa] = pack2(__float2bfloat16(l0), __float2bfloat16(l1));
            h = split_hi(b0, b1, l0, l1);
            *(unsigned*)&dh[offb] = h;
            *(unsigned*)&dl[offb] = pack2(__float2bfloat16(l0), __float2bfloat16(l1));
        }
    }
}

// ============ qb via HMMA: q'_r = q @ bili[r,n] -> slot 1+r (hi only) ============
#define QB_QH 0
#define QB_QL 16384
#define QB_BH 32768
#define QB_BL 40960
#define QB_SMEM 49152

__global__ __launch_bounds__(256) void qb_mma_kernel(const float* __restrict__ bili)
{
    extern __shared__ char smem[];
    const uint32_t sbase = smem_to_u32(smem);
    const int it = blockIdx.x, bn = blockIdx.y, r = blockIdx.z;
    const int n = bn % NH;
    const int tid = threadIdx.x, wid = tid >> 5, lane = tid & 31;
    const int m0 = wid * 16;
    const int rowA = m0 + (lane & 15);
    const int selA = lane >> 4;
    const int rowB8 = lane & 7;
    const int selB = (lane >> 3) & 1;
    const int c2 = 2 * (lane & 3);

#pragma unroll
    for (int c = 0; c < 8; c++) {
        int idx = tid + 256 * c;
        int half = idx >> 10;
        int rem = idx & 1023;
        int row = rem >> 3, ch = rem & 7;
        const __nv_bfloat16* src = (half ? g_ql : g_qh) +
            ((size_t)bn * SQ + it * 128 + row) * DH + ch * 8;
        *(uint4*)(smem + (half ? QB_QL : QB_QH) + SWZ8(row, ch)) = *(const uint4*)src;
    }
    const float* bb = bili + ((size_t)r * NH + n) * DH * DH;
#pragma unroll
    for (int c = 0; c < 16; c++) {
        int id = tid + 256 * c;
        int p = id >> 6, t = id & 63;
        float v = bb[p * 64 + t];
        __nv_bfloat16 hv = __float2bfloat16(v);
        float lo = v - __bfloat162float(hv);
        uint32_t byteoff = SWZ8(t, p >> 3) + (p & 7) * 2;
        *(__nv_bfloat16*)(smem + QB_BH + byteoff) = hv;
        *(__nv_bfloat16*)(smem + QB_BL + byteoff) = __float2bfloat16(lo);
    }
    __syncthreads();

    float fin[32];
#pragma unroll
    for (int e = 0; e < 32; e++) fin[e] = 0.f;

#pragma unroll
    for (int ks = 0; ks < 4; ks++) {
        uint32_t Ah[4], Al[4];
        ldsm_x4(Ah, sbase + QB_QH + SWZ8(rowA, ks * 2 + selA));
        ldsm_x4(Al, sbase + QB_QL + SWZ8(rowA, ks * 2 + selA));
#pragma unroll
        for (int nf = 0; nf < 8; nf++) {
            uint32_t Bh[2], Bl[2];
            ldsm_x2(Bh, sbase + QB_BH + SWZ8(nf * 8 + rowB8, ks * 2 + selB));
            ldsm_x2(Bl, sbase + QB_BL + SWZ8(nf * 8 + rowB8, ks * 2 + selB));
            mma16816(fin + nf * 4, Ah, Bh);
            mma16816(fin + nf * 4, Ah, Bl);
            mma16816(fin + nf * 4, Al, Bh);
        }
    }

    const int slot = 1 + r;
    const int ia = it * 128 + m0 + (lane >> 2);
    const int ib = ia + 8;
#pragma unroll
    for (int nf = 0; nf < 8; nf++) {
        int col = nf * 8 + c2;
        size_t offa = (((size_t)slot * BN + bn) * SQ + ia) * DH + col;
        size_t offb = (((size_t)slot * BN + bn) * SQ + ib) * DH + col;
        *(unsigned*)&g_qh[offa] = pack2(__float2bfloat16(fin[nf * 4 + 0]), __float2bfloat16(fin[nf * 4 + 1]));
        *(unsigned*)&g_qh[offb] = pack2(__float2bfloat16(fin[nf * 4 + 2]), __float2bfloat16(fin[nf * 4 + 3]));
    }
}

// ============ transpose+convert V -> g_vth/g_vtl [bn][d][s] ============
__global__ __launch_bounds__(256) void vt_kernel()
{
    const int st = blockIdx.x, bn = blockIdx.y;
    __shared__ float tile[64][65];
    const int t = threadIdx.x;
#pragma unroll
    for (int c = 0; c < 4; c++) {
        int id = t + 256 * c, row = id >> 4, c4 = (id & 15) << 2;
        float4 v = *(const float4*)&g_v[((size_t)bn * SQ + st * 64 + row) * DH + c4];
        tile[row][c4 + 0] = v.x; tile[row][c4 + 1] = v.y;
        tile[row][c4 + 2] = v.z; tile[row][c4 + 3] = v.w;
    }
    __syncthreads();
#pragma unroll
    for (int c = 0; c < 4; c++) {
        int id = t + 256 * c, d = id >> 4, s4 = (id & 15) << 2;
        float f0 = tile[s4 + 0][d], f1 = tile[s4 + 1][d];
        float f2 = tile[s4 + 2][d], f3 = tile[s4 + 3][d];
        float l0, l1, l2, l3;
        uint2 hv, lv;
        hv.x = split_hi(f0, f1, l0, l1);
        hv.y = split_hi(f2, f3, l2, l3);
        lv.x = pack2(__float2bfloat16(l0), __float2bfloat16(l1));
        lv.y = pack2(__float2bfloat16(l2), __float2bfloat16(l3));
        size_t off = ((size_t)bn * DH + d) * SQ + st * 64 + s4;
        *(uint2*)&g_vth[off] = hv;
        *(uint2*)&g_vtl[off] = lv;
    }
}

// ============ pack adj -> bitmask [r][b][jword][i] ============
__global__ __launch_bounds__(256) void pack_kernel(const float* __restrict__ adj)
{
    const int jw = blockIdx.x, b = blockIdx.y, r = blockIdx.z;
#pragma unroll
    for (int ii = 0; ii < 8; ii++) {
        int i = threadIdx.x + 256 * ii;
        const float* src = adj + (((size_t)(r * BB + b)) * SQ + i) * SQ + jw * 32;
        unsigned bits = 0;
#pragma unroll
        for (int e8 = 0; e8 < 8; e8++) {
            float4 v = *(const float4*)(src + e8 * 4);
            bits |= (unsigned)(v.x != 0.f) << (e8 * 4 + 0);
            bits |= (unsigned)(v.y != 0.f) << (e8 * 4 + 1);
            bits |= (unsigned)(v.z != 0.f) << (e8 * 4 + 2);
            bits |= (unsigned)(v.w != 0.f) << (e8 * 4 + 3);
        }
        g_adjbits[((size_t)(r * BB + b) * 64 + jw) * SQ + i] = bits;
    }
}

// ============ fused flash (score + softmax + ctx) ============
// grid (NH, SQ/64, BB), block 128 (4 warps x 16 rows). 2 CTAs/SM.
#define FQ0H 0
#define FQ0L 8192
#define FQS(s)    (((s) + 1) * 8192)        // s in 1..5
#define FKT(half) (57344 + (half) * 8192)
#define FVT(half) (73728 + (half) * 8192)
#define FL_SMEM   90112

__global__ __launch_bounds__(128) void flash_kernel(
    const float* __restrict__ absb, const float* __restrict__ mask,
    float* __restrict__ out)
{
    extern __shared__ char smem[];
    const uint32_t sbase = smem_to_u32(smem);
    const int n = blockIdx.x, it = blockIdx.y, b = blockIdx.z;
    const int bn = b * NH + n;
    const int i0 = it * 64;
    const int tid = threadIdx.x, wid = tid >> 5, lane = tid & 31;
    const int m0 = wid * 16;

    // ---- load 7 Q tiles (64x64 bf16, swizzled): slot0 h+l, slots1-5 hi ----
#pragma unroll
    for (int c = 0; c < 28; c++) {
        int idx = tid + 128 * c;
        int tile = idx >> 9;
        int rem = idx & 511;
        int row = rem >> 3, ch = rem & 7;
        int slot = (tile <= 1) ? 0 : (tile - 1);
        const __nv_bfloat16* base = (tile == 1) ? g_ql : g_qh;
        const __nv_bfloat16* src = base +
            (((size_t)slot * BN + bn) * SQ + i0 + row) * DH + ch * 8;
        *(uint4*)(smem + tile * 8192 + SWZ8(row, ch)) = *(const uint4*)src;
    }

    const int rowA = m0 + (lane & 15);
    const int selA = lane >> 4;
    const int rowB8 = lane & 7;
    const int selB = (lane >> 3) & 1;
    const int ksB  = lane >> 4;          // selects +0/+1 chunk within x4 B loads
    const int c2 = 2 * (lane & 3);
    const int ia = i0 + m0 + (lane >> 2);
    const int ib = ia + 8;

    float ab[RR];
#pragma unroll
    for (int r = 0; r < RR; r++) ab[r] = absb[r * NH + n];
    const float* maskb = mask + b * SQ;

    float O[32];
#pragma unroll
    for (int e = 0; e < 32; e++) O[e] = 0.f;
    float mr[2] = {-1e30f, -1e30f};
    float lr[2] = {0.f, 0.f};

    for (int jt = 0; jt < 32; jt++) {
        __syncthreads();
        // ---- load K hi/lo (64x64) and Vt hi/lo (64d x 64j) ----
#pragma unroll
        for (int c = 0; c < 16; c++) {
            int idx = tid + 128 * c;
            int seg = idx >> 9;             // 0:kh 1:kl 2:vh 3:vl
            int rem = idx & 511;
            int row = rem >> 3, ch = rem & 7;
            const __nv_bfloat16* src;
            uint32_t dstoff;
            if (seg < 2) {
                src = (seg ? g_kl : g_kh) + ((size_t)bn * SQ + jt * 64 + row) * DH + ch * 8;
                dstoff = FKT(seg);
            } else {
                src = ((seg == 3) ? g_vtl : g_vth) + ((size_t)bn * DH + row) * SQ + jt * 64 + ch * 8;
                dstoff = FVT(seg - 2);
            }
            *(uint4*)(smem + dstoff + SWZ8(row, ch)) = *(const uint4*)src;
        }
        __syncthreads();

        // ---- QK: full 64 cols into fin[32] ----
        float fin[32];
#pragma unroll
        for (int jh = 0; jh < 2; jh++) {
            // hoisted B fragments, x4 loads: BKh[ksp][nf][0..1]=chunk 2ksp(+ksB), [2..3]=2ksp+1
            uint32_t BKh[2][4][4], BKl[2][4][4];
#pragma unroll
            for (int ksp = 0; ksp < 2; ksp++)
#pragma unroll
                for (int nf = 0; nf < 4; nf++) {
                    uint32_t baddr = SWZ8(jh * 32 + nf * 8 + rowB8, (2 * ksp + ksB) * 2 + selB);
                    ldsm_x4(BKh[ksp][nf], sbase + FKT(0) + baddr);
                    ldsm_x4(BKl[ksp][nf], sbase + FKT(1) + baddr);
                }

            const int jw = jt * 2 + jh;
            unsigned aw1[RR], aw2[RR];
#pragma unroll
            for (int r = 0; r < RR; r++) {
                aw1[r] = g_adjbits[((size_t)(r * BB + b) * 64 + jw) * SQ + ia];
                aw2[r] = g_adjbits[((size_t)(r * BB + b) * 64 + jw) * SQ + ib];
            }

            // slot 0: hi/lo 3-pass, A loaded per ks
            float facc[16] = {};
#pragma unroll
            for (int ks = 0; ks < 4; ks++) {
                uint32_t Ah[4], Al[4];
                ldsm_x4(Ah, sbase + FQ0H + SWZ8(rowA, ks * 2 + selA));
                ldsm_x4(Al, sbase + FQ0L + SWZ8(rowA, ks * 2 + selA));
                const int ksp = ks >> 1, off = (ks & 1) * 2;
#pragma unroll
                for (int nf = 0; nf < 4; nf++) {
                    mma16816(facc + nf * 4, Ah, &BKh[ksp][nf][off]);
                    mma16816(facc + nf * 4, Ah, &BKl[ksp][nf][off]);
                    mma16816(facc + nf * 4, Al, &BKh[ksp][nf][off]);
                }
            }

            // slots 1..5: hi-only
#pragma unroll
            for (int s = 1; s < 6; s++) {
                float tmp[16] = {};
#pragma unroll
                for (int ks = 0; ks < 4; ks++) {
                    uint32_t Ah[4];
                    ldsm_x4(Ah, sbase + FQS(s) + SWZ8(rowA, ks * 2 + selA));
                    const int ksp = ks >> 1, off = (ks & 1) * 2;
#pragma unroll
                    for (int nf = 0; nf < 4; nf++)
                        mma16816(tmp + nf * 4, Ah, &BKh[ksp][nf][off]);
                }
                const int r = s - 1;
                const float abr = ab[r];
#pragma unroll
                for (int nf = 0; nf < 4; nf++) {
                    int sh = nf * 8 + c2;
                    if ((aw1[r] >> sh) & 1)       facc[nf * 4 + 0] += tmp[nf * 4 + 0] + abr;
                    if ((aw1[r] >> (sh + 1)) & 1) facc[nf * 4 + 1] += tmp[nf * 4 + 1] + abr;
                    if ((aw2[r] >> sh) & 1)       facc[nf * 4 + 2] += tmp[nf * 4 + 2] + abr;
                    if ((aw2[r] >> (sh + 1)) & 1) facc[nf * 4 + 3] += tmp[nf * 4 + 3] + abr;
                }
            }
#pragma unroll
            for (int e = 0; e < 16; e++) fin[jh * 16 + e] = facc[e];
        }

        // ---- scale + mask (one pass over 64 cols) ----
#pragma unroll
        for (int q = 0; q < 8; q++) {
            int jh = q >> 2, nf = q & 3;
            float2 mk = __ldg((const float2*)&maskb[jt * 64 + jh * 32 + nf * 8 + c2]);
            fin[q * 4 + 0] = fin[q * 4 + 0] * 0.125f + mk.x;
            fin[q * 4 + 1] = fin[q * 4 + 1] * 0.125f + mk.y;
            fin[q * 4 + 2] = fin[q * 4 + 2] * 0.125f + mk.x;
            fin[q * 4 + 3] = fin[q * 4 + 3] * 0.125f + mk.y;
        }

        // ---- single online-softmax update over 64 cols ----
        float mxa = -1e30f, mxb = -1e30f;
#pragma unroll
        for (int q = 0; q < 8; q++) {
            mxa = fmaxf(mxa, fmaxf(fin[q * 4 + 0], fin[q * 4 + 1]));
            mxb = fmaxf(mxb, fmaxf(fin[q * 4 + 2], fin[q * 4 + 3]));
        }
        mxa = fmaxf(mxa, __shfl_xor_sync(0xffffffffu, mxa, 1));
        mxa = fmaxf(mxa, __shfl_xor_sync(0xffffffffu, mxa, 2));
        mxb = fmaxf(mxb, __shfl_xor_sync(0xffffffffu, mxb, 1));
        mxb = fmaxf(mxb, __shfl_xor_sync(0xffffffffu, mxb, 2));
        float mna = fmaxf(mr[0], mxa), mnb = fmaxf(mr[1], mxb);
        float ala = __expf(mr[0] - mna), alb = __expf(mr[1] - mnb);
        mr[0] = mna; mr[1] = mnb;

        float sa = 0.f, sb = 0.f;
#pragma unroll
        for (int q = 0; q < 8; q++) {
            fin[q * 4 + 0] = __expf(fin[q * 4 + 0] - mna);
            fin[q * 4 + 1] = __expf(fin[q * 4 + 1] - mna);
            fin[q * 4 + 2] = __expf(fin[q * 4 + 2] - mnb);
            fin[q * 4 + 3] = __expf(fin[q * 4 + 3] - mnb);
            sa += fin[q * 4 + 0] + fin[q * 4 + 1];
            sb += fin[q * 4 + 2] + fin[q * 4 + 3];
        }
        sa += __shfl_xor_sync(0xffffffffu, sa, 1);
        sa += __shfl_xor_sync(0xffffffffu, sa, 2);
        sb += __shfl_xor_sync(0xffffffffu, sb, 1);
        sb += __shfl_xor_sync(0xffffffffu, sb, 2);
        lr[0] = lr[0] * ala + sa;
        lr[1] = lr[1] * alb + sb;

#pragma unroll
        for (int dn = 0; dn < 8; dn++) {
            O[dn * 4 + 0] *= ala; O[dn * 4 + 1] *= ala;
            O[dn * 4 + 2] *= alb; O[dn * 4 + 3] *= alb;
        }

        // ---- pack P (K=64 -> 4 k-chunks) ----
        uint32_t Ph[4][4], Pl[4][4];
#pragma unroll
        for (int jk = 0; jk < 4; jk++) {
            int jh = jk >> 1, jj = jk & 1;
            int b0 = jh * 16 + (2 * jj) * 4;
            int b1 = jh * 16 + (2 * jj + 1) * 4;
            float l0, l1;
            Ph[jk][0] = split_hi(fin[b0 + 0], fin[b0 + 1], l0, l1);
            Pl[jk][0] = pack2(__float2bfloat16(l0), __float2bfloat16(l1));
            Ph[jk][1] = split_hi(fin[b0 + 2], fin[b0 + 3], l0, l1);
            Pl[jk][1] = pack2(__float2bfloat16(l0), __float2bfloat16(l1));
            Ph[jk][2] = split_hi(fin[b1 + 0], fin[b1 + 1], l0, l1);
            Pl[jk][2] = pack2(__float2bfloat16(l0), __float2bfloat16(l1));
            Ph[jk][3] = split_hi(fin[b1 + 2], fin[b1 + 3], l0, l1);
            Pl[jk][3] = pack2(__float2bfloat16(l0), __float2bfloat16(l1));
        }

        // ---- P @ V: x4 B loads (two d-fragments per ldsm) ----
#pragma unroll
        for (int jk = 0; jk < 4; jk++) {
#pragma unroll
            for (int dnp = 0; dnp < 4; dnp++) {
                uint32_t BVh[4], BVl[4];
                uint32_t vaddr = SWZ8((2 * dnp + ksB) * 8 + rowB8, jk * 2 + selB);
                ldsm_x4(BVh, sbase + FVT(0) + vaddr);
                ldsm_x4(BVl, sbase + FVT(1) + vaddr);
                mma16816(O + (2 * dnp + 0) * 4, Ph[jk], BVh + 0);
                mma16816(O + (2 * dnp + 0) * 4, Ph[jk], BVl + 0);
                mma16816(O + (2 * dnp + 0) * 4, Pl[jk], BVh + 0);
                mma16816(O + (2 * dnp + 1) * 4, Ph[jk], BVh + 2);
                mma16816(O + (2 * dnp + 1) * 4, Ph[jk], BVl + 2);
                mma16816(O + (2 * dnp + 1) * 4, Pl[jk], BVh + 2);
            }
        }
    }

    const float inva = 1.0f / lr[0], invb = 1.0f / lr[1];
#pragma unroll
    for (int dn = 0; dn < 8; dn++) {
        int d = dn * 8 + c2;
        float2 oa, ob;
        oa.x = O[dn * 4 + 0] * inva; oa.y = O[dn * 4 + 1] * inva;
        ob.x = O[dn * 4 + 2] * invb; ob.y = O[dn * 4 + 3] * invb;
        *(float2*)&out[((size_t)b * SQ + ia) * HID + n * 64 + d] = oa;
        *(float2*)&out[((size_t)b * SQ + ib) * HID + n * 64 + d] = ob;
    }
}

// =================================================================
extern "C" void kernel_launch(void* const* d_in, const int* in_sizes, int n_in,
                              void* d_out, int out_size)
{
    const float* hidden = (const float*)d_in[0];
    const float* mask   = (const float*)d_in[1];
    const float* adj    = (const float*)d_in[2];
    const float* Wq     = (const float*)d_in[3];
    const float* bq     = (const float*)d_in[4];
    const float* Wk     = (const float*)d_in[5];
    const float* bk     = (const float*)d_in[6];
    const float* Wv     = (const float*)d_in[7];
    const float* bv     = (const float*)d_in[8];
    const float* bili   = (const float*)d_in[9];
    const float* absb   = (const float*)d_in[10];
    float* out = (float*)d_out;
    (void)in_sizes; (void)n_in; (void)out_size;

    cudaFuncSetAttribute(proj_mma_kernel, cudaFuncAttributeMaxDynamicSharedMemorySize, PJ_SMEM);
    cudaFuncSetAttribute(qb_mma_kernel, cudaFuncAttributeMaxDynamicSharedMemorySize, QB_SMEM);
    cudaFuncSetAttribute(flash_kernel, cudaFuncAttributeMaxDynamicSharedMemorySize, FL_SMEM);

    convx_kernel<<<BB * SQ * HID / 4 / 256, 256>>>(hidden);
    convw_kernel<<<3 * HID * HID / 4 / 256, 256>>>(Wq, Wk, Wv);
    proj_mma_kernel<<<dim3(HID / 64, BB * SQ / 128, 3), 256, PJ_SMEM>>>(bq, bk, bv);
    qb_mma_kernel<<<dim3(SQ / 128, BN, RR), 256, QB_SMEM>>>(bili);
    vt_kernel<<<dim3(SQ / 64, BN), 256>>>();
    pack_kernel<<<dim3(SQ / 32, BB, RR), 256>>>(adj);
    flash_kernel<<<dim3(NH, SQ / 64, BB), 128, FL_SMEM>>>(absb, mask, out);
}

// round 10
// speedup vs baseline: 1.1022x; 1.0983x over previous
#include <cuda_runtime.h>
#include <cuda_bf16.h>
#include <cstdint>
#include <math.h>

#define SQ   2048
#define HID  768
#define BB   2
#define NH   12
#define DH   64
#define RR   5
#define BN   24

// ---------------- device scratch ----------------
__device__ float g_v   [(size_t)BN * SQ * DH];
__device__ __nv_bfloat16 g_xh[(size_t)BB * SQ * HID];
__device__ __nv_bfloat16 g_xl[(size_t)BB * SQ * HID];
__device__ __nv_bfloat16 g_wh[(size_t)3 * HID * HID];
__device__ __nv_bfloat16 g_wl[(size_t)3 * HID * HID];
__device__ __nv_bfloat16 g_qh[(size_t)6 * BN * SQ * DH];   // slot 0..5 hi
__device__ __nv_bfloat16 g_ql[(size_t)BN * SQ * DH];       // slot 0 lo only
__device__ __nv_bfloat16 g_kh[(size_t)BN * SQ * DH];
__device__ __nv_bfloat16 g_kl[(size_t)BN * SQ * DH];
__device__ __nv_bfloat16 g_vth[(size_t)BN * DH * SQ];      // V^T [bn][d][s] hi
__device__ __nv_bfloat16 g_vtl[(size_t)BN * DH * SQ];      // V^T [bn][d][s] lo
__device__ unsigned g_adjbits[(size_t)RR * BB * (SQ / 32) * SQ];

// ================= helpers =================
__device__ __forceinline__ uint32_t smem_to_u32(const void* p) {
    uint32_t a;
    asm("{ .reg .u64 t; cvta.to.shared.u64 t, %1; cvt.u32.u64 %0, t; }" : "=r"(a) : "l"(p));
    return a;
}
__device__ __forceinline__ unsigned pack2(__nv_bfloat16 a, __nv_bfloat16 b) {
    __nv_bfloat162 t; t.x = a; t.y = b;
    return *reinterpret_cast<unsigned*>(&t);
}
__device__ __forceinline__ void ldsm_x4(uint32_t* r, uint32_t addr) {
    asm volatile("ldmatrix.sync.aligned.m8n8.x4.shared.b16 {%0,%1,%2,%3}, [%4];"
        : "=r"(r[0]), "=r"(r[1]), "=r"(r[2]), "=r"(r[3]) : "r"(addr));
}
__device__ __forceinline__ void ldsm_x2(uint32_t* r, uint32_t addr) {
    asm volatile("ldmatrix.sync.aligned.m8n8.x2.shared.b16 {%0,%1}, [%2];"
        : "=r"(r[0]), "=r"(r[1]) : "r"(addr));
}
__device__ __forceinline__ void mma16816(float* d, const uint32_t* a, const uint32_t* b) {
    asm volatile(
        "mma.sync.aligned.m16n8k16.row.col.f32.bf16.bf16.f32 "
        "{%0,%1,%2,%3}, {%4,%5,%6,%7}, {%8,%9}, {%0,%1,%2,%3};"
        : "+f"(d[0]), "+f"(d[1]), "+f"(d[2]), "+f"(d[3])
        : "r"(a[0]), "r"(a[1]), "r"(a[2]), "r"(a[3]), "r"(b[0]), "r"(b[1]));
}
__device__ __forceinline__ unsigned split_hi(float x, float y, float& lx, float& ly) {
    __nv_bfloat16 hx = __float2bfloat16(x), hy = __float2bfloat16(y);
    lx = x - __bfloat162float(hx);
    ly = y - __bfloat162float(hy);
    return pack2(hx, hy);
}
__device__ __forceinline__ void cpa16(uint32_t dst, const void* src) {
    asm volatile("cp.async.cg.shared.global [%0], [%1], 16;" :: "r"(dst), "l"(src));
}
#define CP_COMMIT() asm volatile("cp.async.commit_group;" ::: "memory")
#define CP_WAIT(n)  asm volatile("cp.async.wait_group %0;" :: "n"(n) : "memory")
#define SWZ8(row, ch)   (((row) * 128) + ((((ch) ^ ((row) & 7))) << 4))

// ============ conv X -> bf16 hi/lo ============
__global__ __launch_bounds__(256) void convx_kernel(const float* __restrict__ X)
{
    int c = blockIdx.x * 256 + threadIdx.x;
    float4 v = ((const float4*)X)[c];
    float lx, ly, lz, lw;
    uint2 h, l;
    h.x = split_hi(v.x, v.y, lx, ly);
    h.y = split_hi(v.z, v.w, lz, lw);
    l.x = pack2(__float2bfloat16(lx), __float2bfloat16(ly));
    l.y = pack2(__float2bfloat16(lz), __float2bfloat16(lw));
    ((uint2*)g_xh)[c] = h;
    ((uint2*)g_xl)[c] = l;
}

// ============ conv W (q,k,v) -> bf16 hi/lo ============
__global__ __launch_bounds__(256) void convw_kernel(
    const float* __restrict__ Wq, const float* __restrict__ Wk, const float* __restrict__ Wv)
{
    const int per = HID * HID / 4;
    int c = blockIdx.x * 256 + threadIdx.x;
    int z = c / per;
    const float* W = (z == 0) ? Wq : (z == 1) ? Wk : Wv;
    float4 v = ((const float4*)W)[c - z * per];
    float lx, ly, lz, lw;
    uint2 h, l;
    h.x = split_hi(v.x, v.y, lx, ly);
    h.y = split_hi(v.z, v.w, lz, lw);
    l.x = pack2(__float2bfloat16(lx), __float2bfloat16(ly));
    l.y = pack2(__float2bfloat16(lz), __float2bfloat16(lw));
    ((uint2*)g_wh)[c] = h;
    ((uint2*)g_wl)[c] = l;
}

// ============ proj via HMMA: out = X @ W^T + b ============
#define PJ_XH 0
#define PJ_XL 16384
#define PJ_WH 32768
#define PJ_WL 40960
#define PJ_SMEM 49152

__global__ __launch_bounds__(256) void proj_mma_kernel(
    const float* __restrict__ bq, const float* __restrict__ bk, const float* __restrict__ bv)
{
    extern __shared__ char smem[];
    const uint32_t sbase = smem_to_u32(smem);
    const int otile = blockIdx.x, mtile = blockIdx.y, z = blockIdx.z;
    const float* bias = (z == 0) ? bq : (z == 1) ? bk : bv;
    const int tid = threadIdx.x, wid = tid >> 5, lane = tid & 31;
    const int m0 = wid * 16;
    const int rowA = m0 + (lane & 15);
    const int selA = lane >> 4;
    const int rowB8 = lane & 7;
    const int selB = (lane >> 3) & 1;
    const int c2 = 2 * (lane & 3);

    float fin[32];
#pragma unroll
    for (int e = 0; e < 32; e++) fin[e] = 0.f;

    for (int kc = 0; kc < HID / 64; kc++) {
        __syncthreads();
#pragma unroll
        for (int c = 0; c < 8; c++) {
            int idx = tid + 256 * c;
            int half = idx >> 10;
            int rem = idx & 1023;
            int row = rem >> 3, ch = rem & 7;
            const __nv_bfloat16* src = (half ? g_xl : g_xh) +
                (size_t)(mtile * 128 + row) * HID + kc * 64 + ch * 8;
            *(uint4*)(smem + (half ? PJ_XL : PJ_XH) + SWZ8(row, ch)) = *(const uint4*)src;
        }
#pragma unroll
        for (int c = 0; c < 4; c++) {
            int idx = tid + 256 * c;
            int half = idx >> 9;
            int rem = idx & 511;
            int row = rem >> 3, ch = rem & 7;
            const __nv_bfloat16* src = (half ? g_wl : g_wh) +
                ((size_t)z * HID + otile * 64 + row) * HID + kc * 64 + ch * 8;
            *(uint4*)(smem + (half ? PJ_WL : PJ_WH) + SWZ8(row, ch)) = *(const uint4*)src;
        }
        __syncthreads();

#pragma unroll
        for (int ks = 0; ks < 4; ks++) {
            uint32_t Ah[4], Al[4];
            ldsm_x4(Ah, sbase + PJ_XH + SWZ8(rowA, ks * 2 + selA));
            ldsm_x4(Al, sbase + PJ_XL + SWZ8(rowA, ks * 2 + selA));
#pragma unroll
            for (int nf = 0; nf < 8; nf++) {
                uint32_t Bh[2], Bl[2];
                ldsm_x2(Bh, sbase + PJ_WH + SWZ8(nf * 8 + rowB8, ks * 2 + selB));
                ldsm_x2(Bl, sbase + PJ_WL + SWZ8(nf * 8 + rowB8, ks * 2 + selB));
                mma16816(fin + nf * 4, Ah, Bh);
                mma16816(fin + nf * 4, Ah, Bl);
                mma16816(fin + nf * 4, Al, Bh);
            }
        }
    }

    const int ma = mtile * 128 + m0 + (lane >> 2);
    const int b = ma >> 11;
    const int sa = ma & (SQ - 1), sb = sa + 8;
    const int bn = b * NH + otile;
#pragma unroll
    for (int nf = 0; nf < 8; nf++) {
        int col = nf * 8 + c2;
        float bsx = bias[otile * 64 + col], bsy = bias[otile * 64 + col + 1];
        float a0 = fin[nf * 4 + 0] + bsx, a1 = fin[nf * 4 + 1] + bsy;
        float b0 = fin[nf * 4 + 2] + bsx, b1 = fin[nf * 4 + 3] + bsy;
        size_t offa = ((size_t)bn * SQ + sa) * DH + col;
        size_t offb = ((size_t)bn * SQ + sb) * DH + col;
        if (z == 2) {
            *(float2*)&g_v[offa] = make_float2(a0, a1);
            *(float2*)&g_v[offb] = make_float2(b0, b1);
        } else {
            __nv_bfloat16* dh = (z == 0) ? g_qh : g_kh;
            __nv_bfloat16* dl = (z == 0) ? g_ql : g_kl;
            float l0, l1;
            unsigned h;
            h = split_hi(a0, a1, l0, l1);
            *(unsigned*)&dh[offa] = h;
            *(unsigned*)&dl[offa] = pack2(__float2bfloat16(l0), __float2bfloat16(l1));
            h = split_hi(b0, b1, l0, l1);
            *(unsigned*)&dh[offb] = h;
            *(unsigned*)&dl[offb] = pack2(__float2bfloat16(l0), __float2bfloat16(l1));
        }
    }
}

// ============ qb via HMMA: q'_r = q @ bili[r,n] -> slot 1+r (hi only) ============
#define QB_QH 0
#define QB_QL 16384
#define QB_BH 32768
#define QB_BL 40960
#define QB_SMEM 49152

__global__ __launch_bounds__(256) void qb_mma_kernel(const float* __restrict__ bili)
{
    extern __shared__ char smem[];
    const uint32_t sbase = smem_to_u32(smem);
    const int it = blockIdx.x, bn = blockIdx.y, r = blockIdx.z;
    const int n = bn % NH;
    const int tid = threadIdx.x, wid = tid >> 5, lane = tid & 31;
    const int m0 = wid * 16;
    const int rowA = m0 + (lane & 15);
    const int selA = lane >> 4;
    const int rowB8 = lane & 7;
    const int selB = (lane >> 3) & 1;
    const int c2 = 2 * (lane & 3);

#pragma unroll
    for (int c = 0; c < 8; c++) {
        int idx = tid + 256 * c;
        int half = idx >> 10;
        int rem = idx & 1023;
        int row = rem >> 3, ch = rem & 7;
        const __nv_bfloat16* src = (half ? g_ql : g_qh) +
            ((size_t)bn * SQ + it * 128 + row) * DH + ch * 8;
        *(uint4*)(smem + (half ? QB_QL : QB_QH) + SWZ8(row, ch)) = *(const uint4*)src;
    }
    const float* bb = bili + ((size_t)r * NH + n) * DH * DH;
#pragma unroll
    for (int c = 0; c < 16; c++) {
        int id = tid + 256 * c;
        int p = id >> 6, t = id & 63;
        float v = bb[p * 64 + t];
        __nv_bfloat16 hv = __float2bfloat16(v);
        float lo = v - __bfloat162float(hv);
        uint32_t byteoff = SWZ8(t, p >> 3) + (p & 7) * 2;
        *(__nv_bfloat16*)(smem + QB_BH + byteoff) = hv;
        *(__nv_bfloat16*)(smem + QB_BL + byteoff) = __float2bfloat16(lo);
    }
    __syncthreads();

    float fin[32];
#pragma unroll
    for (int e = 0; e < 32; e++) fin[e] = 0.f;

#pragma unroll
    for (int ks = 0; ks < 4; ks++) {
        uint32_t Ah[4], Al[4];
        ldsm_x4(Ah, sbase + QB_QH + SWZ8(rowA, ks * 2 + selA));
        ldsm_x4(Al, sbase + QB_QL + SWZ8(rowA, ks * 2 + selA));
#pragma unroll
        for (int nf = 0; nf < 8; nf++) {
            uint32_t Bh[2], Bl[2];
            ldsm_x2(Bh, sbase + QB_BH + SWZ8(nf * 8 + rowB8, ks * 2 + selB));
            ldsm_x2(Bl, sbase + QB_BL + SWZ8(nf * 8 + rowB8, ks * 2 + selB));
            mma16816(fin + nf * 4, Ah, Bh);
            mma16816(fin + nf * 4, Ah, Bl);
            mma16816(fin + nf * 4, Al, Bh);
        }
    }

    const int slot = 1 + r;
    const int ia = it * 128 + m0 + (lane >> 2);
    const int ib = ia + 8;
#pragma unroll
    for (int nf = 0; nf < 8; nf++) {
        int col = nf * 8 + c2;
        size_t offa = (((size_t)slot * BN + bn) * SQ + ia) * DH + col;
        size_t offb = (((size_t)slot * BN + bn) * SQ + ib) * DH + col;
        *(unsigned*)&g_qh[offa] = pack2(__float2bfloat16(fin[nf * 4 + 0]), __float2bfloat16(fin[nf * 4 + 1]));
        *(unsigned*)&g_qh[offb] = pack2(__float2bfloat16(fin[nf * 4 + 2]), __float2bfloat16(fin[nf * 4 + 3]));
    }
}

// ============ transpose+convert V -> g_vth/g_vtl [bn][d][s] ============
__global__ __launch_bounds__(256) void vt_kernel()
{
    const int st = blockIdx.x, bn = blockIdx.y;
    __shared__ float tile[64][65];
    const int t = threadIdx.x;
#pragma unroll
    for (int c = 0; c < 4; c++) {
        int id = t + 256 * c, row = id >> 4, c4 = (id & 15) << 2;
        float4 v = *(const float4*)&g_v[((size_t)bn * SQ + st * 64 + row) * DH + c4];
        tile[row][c4 + 0] = v.x; tile[row][c4 + 1] = v.y;
        tile[row][c4 + 2] = v.z; tile[row][c4 + 3] = v.w;
    }
    __syncthreads();
#pragma unroll
    for (int c = 0; c < 4; c++) {
        int id = t + 256 * c, d = id >> 4, s4 = (id & 15) << 2;
        float f0 = tile[s4 + 0][d], f1 = tile[s4 + 1][d];
        float f2 = tile[s4 + 2][d], f3 = tile[s4 + 3][d];
        float l0, l1, l2, l3;
        uint2 hv, lv;
        hv.x = split_hi(f0, f1, l0, l1);
        hv.y = split_hi(f2, f3, l2, l3);
        lv.x = pack2(__float2bfloat16(l0), __float2bfloat16(l1));
        lv.y = pack2(__float2bfloat16(l2), __float2bfloat16(l3));
        size_t off = ((size_t)bn * DH + d) * SQ + st * 64 + s4;
        *(uint2*)&g_vth[off] = hv;
        *(uint2*)&g_vtl[off] = lv;
    }
}

// ============ pack adj -> bitmask [r][b][jword][i] ============
__global__ __launch_bounds__(256) void pack_kernel(const float* __restrict__ adj)
{
    const int jw = blockIdx.x, b = blockIdx.y, r = blockIdx.z;
#pragma unroll
    for (int ii = 0; ii < 8; ii++) {
        int i = threadIdx.x + 256 * ii;
        const float* src = adj + (((size_t)(r * BB + b)) * SQ + i) * SQ + jw * 32;
        unsigned bits = 0;
#pragma unroll
        for (int e8 = 0; e8 < 8; e8++) {
            float4 v = *(const float4*)(src + e8 * 4);
            bits |= (unsigned)(v.x != 0.f) << (e8 * 4 + 0);
            bits |= (unsigned)(v.y != 0.f) << (e8 * 4 + 1);
            bits |= (unsigned)(v.z != 0.f) << (e8 * 4 + 2);
            bits |= (unsigned)(v.w != 0.f) << (e8 * 4 + 3);
        }
        g_adjbits[((size_t)(r * BB + b) * 64 + jw) * SQ + i] = bits;
    }
}

// ============ fused flash (score + softmax + ctx), cp.async pipelined ============
// grid (NH, SQ/64, BB), block 128 (4 warps x 16 rows). 2 CTAs/SM.
#define FQ0H 0
#define FQ0L 8192
#define FQS(s)    (((s) + 1) * 8192)        // s in 1..5
#define FKT(half) (57344 + (half) * 8192)
#define FVT(half) (73728 + (half) * 8192)
#define FL_SMEM   90112

__global__ __launch_bounds__(128) void flash_kernel(
    const float* __restrict__ absb, const float* __restrict__ mask,
    float* __restrict__ out)
{
    extern __shared__ char smem[];
    const uint32_t sbase = smem_to_u32(smem);
    const int n = blockIdx.x, it = blockIdx.y, b = blockIdx.z;
    const int bn = b * NH + n;
    const int i0 = it * 64;
    const int tid = threadIdx.x, wid = tid >> 5, lane = tid & 31;
    const int m0 = wid * 16;

    // ---- async tile loaders (8 cp.async of 16B per thread each) ----
    auto load_k = [&](int jt) {
#pragma unroll
        for (int c = 0; c < 8; c++) {
            int idx = tid + 128 * c;
            int half = idx >> 9;
            int rem = idx & 511;
            int row = rem >> 3, ch = rem & 7;
            const __nv_bfloat16* src = (half ? g_kl : g_kh) +
                ((size_t)bn * SQ + jt * 64 + row) * DH + ch * 8;
            cpa16(sbase + FKT(half) + SWZ8(row, ch), src);
        }
        CP_COMMIT();
    };
    auto load_v = [&](int jt) {
#pragma unroll
        for (int c = 0; c < 8; c++) {
            int idx = tid + 128 * c;
            int half = idx >> 9;
            int rem = idx & 511;
            int row = rem >> 3, ch = rem & 7;
            const __nv_bfloat16* src = (half ? g_vtl : g_vth) + 0;
            src = (half ? g_vtl : g_vth) + ((size_t)bn * DH + row) * SQ + jt * 64 + ch * 8;
            cpa16(sbase + FVT(half) + SWZ8(row, ch), src);
        }
        CP_COMMIT();
    };

    // prefetch first K and V tiles
    load_k(0);
    load_v(0);

    // ---- load 7 Q tiles (64x64 bf16, swizzled): slot0 h+l, slots1-5 hi ----
#pragma unroll
    for (int c = 0; c < 28; c++) {
        int idx = tid + 128 * c;
        int tile = idx >> 9;
        int rem = idx & 511;
        int row = rem >> 3, ch = rem & 7;
        int slot = (tile <= 1) ? 0 : (tile - 1);
        const __nv_bfloat16* base = (tile == 1) ? g_ql : g_qh;
        const __nv_bfloat16* src = base +
            (((size_t)slot * BN + bn) * SQ + i0 + row) * DH + ch * 8;
        *(uint4*)(smem + tile * 8192 + SWZ8(row, ch)) = *(const uint4*)src;
    }

    const int rowA = m0 + (lane & 15);
    const int selA = lane >> 4;
    const int rowB8 = lane & 7;
    const int selB = (lane >> 3) & 1;
    const int c2 = 2 * (lane & 3);
    const int ia = i0 + m0 + (lane >> 2);
    const int ib = ia + 8;

    float ab[RR];
#pragma unroll
    for (int r = 0; r < RR; r++) ab[r] = absb[r * NH + n];
    const float* maskb = mask + b * SQ;

    float O[32];
#pragma unroll
    for (int e = 0; e < 32; e++) O[e] = 0.f;
    float mr[2] = {-1e30f, -1e30f};
    float lr[2] = {0.f, 0.f};

    for (int jt = 0; jt < 32; jt++) {
        // ---- K(jt) ready (V(jt) may still be in flight) ----
        if (jt < 31) { CP_WAIT(1); } else { CP_WAIT(1); }
        __syncthreads();

        // ---- QK + structural bias over both 32-col halves ----
        float fin[32];
#pragma unroll
        for (int jh = 0; jh < 2; jh++) {
            // hoist K fragments [half][ks][nf][2] (short-lived, x2 loads)
            uint32_t BK[2][4][4][2];
#pragma unroll
            for (int h = 0; h < 2; h++)
#pragma unroll
                for (int ks = 0; ks < 4; ks++)
#pragma unroll
                    for (int nf = 0; nf < 4; nf++)
                        ldsm_x2(BK[h][ks][nf],
                                sbase + FKT(h) + SWZ8(jh * 32 + nf * 8 + rowB8, ks * 2 + selB));

            const int jw = jt * 2 + jh;
            unsigned aw1[RR], aw2[RR];
#pragma unroll
            for (int r = 0; r < RR; r++) {
                aw1[r] = g_adjbits[((size_t)(r * BB + b) * 64 + jw) * SQ + ia];
                aw2[r] = g_adjbits[((size_t)(r * BB + b) * 64 + jw) * SQ + ib];
            }

            // slot 0: hi/lo 3-pass
            float facc[16] = {};
#pragma unroll
            for (int ks = 0; ks < 4; ks++) {
                uint32_t Ah[4], Al[4];
                ldsm_x4(Ah, sbase + FQ0H + SWZ8(rowA, ks * 2 + selA));
                ldsm_x4(Al, sbase + FQ0L + SWZ8(rowA, ks * 2 + selA));
#pragma unroll
                for (int nf = 0; nf < 4; nf++) {
                    mma16816(facc + nf * 4, Ah, BK[0][ks][nf]);
                    mma16816(facc + nf * 4, Ah, BK[1][ks][nf]);
                    mma16816(facc + nf * 4, Al, BK[0][ks][nf]);
                }
            }

            // slots 1..5: hi-only 1-pass
#pragma unroll
            for (int s = 1; s < 6; s++) {
                float tmp[16] = {};
#pragma unroll
                for (int ks = 0; ks < 4; ks++) {
                    uint32_t Ah[4];
                    ldsm_x4(Ah, sbase + FQS(s) + SWZ8(rowA, ks * 2 + selA));
#pragma unroll
                    for (int nf = 0; nf < 4; nf++)
                        mma16816(tmp + nf * 4, Ah, BK[0][ks][nf]);
                }
                const int r = s - 1;
                const float abr = ab[r];
#pragma unroll
                for (int nf = 0; nf < 4; nf++) {
                    int sh = nf * 8 + c2;
                    if ((aw1[r] >> sh) & 1)       facc[nf * 4 + 0] += tmp[nf * 4 + 0] + abr;
                    if ((aw1[r] >> (sh + 1)) & 1) facc[nf * 4 + 1] += tmp[nf * 4 + 1] + abr;
                    if ((aw2[r] >> sh) & 1)       facc[nf * 4 + 2] += tmp[nf * 4 + 2] + abr;
                    if ((aw2[r] >> (sh + 1)) & 1) facc[nf * 4 + 3] += tmp[nf * 4 + 3] + abr;
                }
            }
#pragma unroll
            for (int e = 0; e < 16; e++) fin[jh * 16 + e] = facc[e];
        }

        // all K reads done -> safe to overwrite K buffer
        __syncthreads();
        if (jt < 31) load_k(jt + 1);

        // ---- scale + mask ----
#pragma unroll
        for (int q = 0; q < 8; q++) {
            int jh = q >> 2, nf = q & 3;
            float2 mk = __ldg((const float2*)&maskb[jt * 64 + jh * 32 + nf * 8 + c2]);
            fin[q * 4 + 0] = fin[q * 4 + 0] * 0.125f + mk.x;
            fin[q * 4 + 1] = fin[q * 4 + 1] * 0.125f + mk.y;
            fin[q * 4 + 2] = fin[q * 4 + 2] * 0.125f + mk.x;
            fin[q * 4 + 3] = fin[q * 4 + 3] * 0.125f + mk.y;
        }

        // ---- online softmax over 64 cols ----
        float mxa = -1e30f, mxb = -1e30f;
#pragma unroll
        for (int q = 0; q < 8; q++) {
            mxa = fmaxf(mxa, fmaxf(fin[q * 4 + 0], fin[q * 4 + 1]));
            mxb = fmaxf(mxb, fmaxf(fin[q * 4 + 2], fin[q * 4 + 3]));
        }
        mxa = fmaxf(mxa, __shfl_xor_sync(0xffffffffu, mxa, 1));
        mxa = fmaxf(mxa, __shfl_xor_sync(0xffffffffu, mxa, 2));
        mxb = fmaxf(mxb, __shfl_xor_sync(0xffffffffu, mxb, 1));
        mxb = fmaxf(mxb, __shfl_xor_sync(0xffffffffu, mxb, 2));
        float mna = fmaxf(mr[0], mxa), mnb = fmaxf(mr[1], mxb);
        float ala = __expf(mr[0] - mna), alb = __expf(mr[1] - mnb);
        mr[0] = mna; mr[1] = mnb;

        float sa = 0.f, sb = 0.f;
#pragma unroll
        for (int q = 0; q < 8; q++) {
            fin[q * 4 + 0] = __expf(fin[q * 4 + 0] - mna);
            fin[q * 4 + 1] = __expf(fin[q * 4 + 1] - mna);
            fin[q * 4 + 2] = __expf(fin[q * 4 + 2] - mnb);
            fin[q * 4 + 3] = __expf(fin[q * 4 + 3] - mnb);
            sa += fin[q * 4 + 0] + fin[q * 4 + 1];
            sb += fin[q * 4 + 2] + fin[q * 4 + 3];
        }
        sa += __shfl_xor_sync(0xffffffffu, sa, 1);
        sa += __shfl_xor_sync(0xffffffffu, sa, 2);
        sb += __shfl_xor_sync(0xffffffffu, sb, 1);
        sb += __shfl_xor_sync(0xffffffffu, sb, 2);
        lr[0] = lr[0] * ala + sa;
        lr[1] = lr[1] * alb + sb;

#pragma unroll
        for (int dn = 0; dn < 8; dn++) {
            O[dn * 4 + 0] *= ala; O[dn * 4 + 1] *= ala;
            O[dn * 4 + 2] *= alb; O[dn * 4 + 3] *= alb;
        }

        // ---- pack P (K=64 -> 4 k-chunks) ----
        uint32_t Ph[4][4], Pl[4][4];
#pragma unroll
        for (int jk = 0; jk < 4; jk++) {
            int jh = jk >> 1, jj = jk & 1;
            int b0 = jh * 16 + (2 * jj) * 4;
            int b1 = jh * 16 + (2 * jj + 1) * 4;
            float l0, l1;
            Ph[jk][0] = split_hi(fin[b0 + 0], fin[b0 + 1], l0, l1);
            Pl[jk][0] = pack2(__float2bfloat16(l0), __float2bfloat16(l1));
            Ph[jk][1] = split_hi(fin[b0 + 2], fin[b0 + 3], l0, l1);
            Pl[jk][1] = pack2(__float2bfloat16(l0), __float2bfloat16(l1));
            Ph[jk][2] = split_hi(fin[b1 + 0], fin[b1 + 1], l0, l1);
            Pl[jk][2] = pack2(__float2bfloat16(l0), __float2bfloat16(l1));
            Ph[jk][3] = split_hi(fin[b1 + 2], fin[b1 + 3], l0, l1);
            Pl[jk][3] = pack2(__float2bfloat16(l0), __float2bfloat16(l1));
        }

        // ---- V(jt) ready (only K(jt+1) may remain in flight) ----
        if (jt < 31) { CP_WAIT(1); } else { CP_WAIT(0); }
        __syncthreads();

        // ---- P @ V ----
#pragma unroll
        for (int jk = 0; jk < 4; jk++) {
#pragma unroll
            for (int dn = 0; dn < 8; dn++) {
                uint32_t BVh[2], BVl[2];
                uint32_t vaddr = SWZ8(dn * 8 + rowB8, jk * 2 + selB);
                ldsm_x2(BVh, sbase + FVT(0) + vaddr);
                ldsm_x2(BVl, sbase + FVT(1) + vaddr);
                mma16816(O + dn * 4, Ph[jk], BVh);
                mma16816(O + dn * 4, Ph[jk], BVl);
                mma16816(O + dn * 4, Pl[jk], BVh);
            }
        }

        // all V reads done -> safe to overwrite V buffer
        __syncthreads();
        if (jt < 31) load_v(jt + 1);
    }

    const float inva = 1.0f / lr[0], invb = 1.0f / lr[1];
#pragma unroll
    for (int dn = 0; dn < 8; dn++) {
        int d = dn * 8 + c2;
        float2 oa, ob;
        oa.x = O[dn * 4 + 0] * inva; oa.y = O[dn * 4 + 1] * inva;
        ob.x = O[dn * 4 + 2] * invb; ob.y = O[dn * 4 + 3] * invb;
        *(float2*)&out[((size_t)b * SQ + ia) * HID + n * 64 + d] = oa;
        *(float2*)&out[((size_t)b * SQ + ib) * HID + n * 64 + d] = ob;
    }
}

// =================================================================
extern "C" void kernel_launch(void* const* d_in, const int* in_sizes, int n_in,
                              void* d_out, int out_size)
{
    const float* hidden = (const float*)d_in[0];
    const float* mask   = (const float*)d_in[1];
    const float* adj    = (const float*)d_in[2];
    const float* Wq     = (const float*)d_in[3];
    const float* bq     = (const float*)d_in[4];
    const float* Wk     = (const float*)d_in[5];
    const float* bk     = (const float*)d_in[6];
    const float* Wv     = (const float*)d_in[7];
    const float* bv     = (const float*)d_in[8];
    const float* bili   = (const float*)d_in[9];
    const float* absb   = (const float*)d_in[10];
    float* out = (float*)d_out;
    (void)in_sizes; (void)n_in; (void)out_size;

    cudaFuncSetAttribute(proj_mma_kernel, cudaFuncAttributeMaxDynamicSharedMemorySize, PJ_SMEM);
    cudaFuncSetAttribute(qb_mma_kernel, cudaFuncAttributeMaxDynamicSharedMemorySize, QB_SMEM);
    cudaFuncSetAttribute(flash_kernel, cudaFuncAttributeMaxDynamicSharedMemorySize, FL_SMEM);

    convx_kernel<<<BB * SQ * HID / 4 / 256, 256>>>(hidden);
    convw_kernel<<<3 * HID * HID / 4 / 256, 256>>>(Wq, Wk, Wv);
    proj_mma_kernel<<<dim3(HID / 64, BB * SQ / 128, 3), 256, PJ_SMEM>>>(bq, bk, bv);
    qb_mma_kernel<<<dim3(SQ / 128, BN, RR), 256, QB_SMEM>>>(bili);
    vt_kernel<<<dim3(SQ / 64, BN), 256>>>();
    pack_kernel<<<dim3(SQ / 32, BB, RR), 256>>>(adj);
    flash_kernel<<<dim3(NH, SQ / 64, BB), 128, FL_SMEM>>>(absb, mask, out);
}

// round 14
// speedup vs baseline: 1.2687x; 1.1511x over previous
#include <cuda_runtime.h>
#include <cuda_fp16.h>
#include <cstdint>
#include <math.h>

#define SQ   2048
#define HID  768
#define BB   2
#define NH   12
#define DH   64
#define RR   5
#define BN   24

// ---------------- device scratch ----------------
__device__ float g_v   [(size_t)BN * SQ * DH];
__device__ __half g_xh[(size_t)BB * SQ * HID];
__device__ __half g_xl[(size_t)BB * SQ * HID];
__device__ __half g_wh[(size_t)3 * HID * HID];
__device__ __half g_wl[(size_t)3 * HID * HID];
__device__ __half g_qh[(size_t)6 * BN * SQ * DH];   // slots 0..5, fp16
__device__ __half g_kh[(size_t)BN * SQ * DH];
__device__ __half g_vth[(size_t)BN * DH * SQ];      // V^T [bn][d][s] hi
__device__ __half g_vtl[(size_t)BN * DH * SQ];      // V^T [bn][d][s] lo
__device__ unsigned g_adjbits[(size_t)RR * BB * (SQ / 32) * SQ];

// ================= helpers =================
__device__ __forceinline__ uint32_t smem_to_u32(const void* p) {
    uint32_t a;
    asm("{ .reg .u64 t; cvta.to.shared.u64 t, %1; cvt.u32.u64 %0, t; }" : "=r"(a) : "l"(p));
    return a;
}
__device__ __forceinline__ unsigned pack2(__half a, __half b) {
    __half2 t; t.x = a; t.y = b;
    return *reinterpret_cast<unsigned*>(&t);
}
__device__ __forceinline__ void ldsm_x4(uint32_t* r, uint32_t addr) {
    asm volatile("ldmatrix.sync.aligned.m8n8.x4.shared.b16 {%0,%1,%2,%3}, [%4];"
        : "=r"(r[0]), "=r"(r[1]), "=r"(r[2]), "=r"(r[3]) : "r"(addr));
}
__device__ __forceinline__ void ldsm_x2(uint32_t* r, uint32_t addr) {
    asm volatile("ldmatrix.sync.aligned.m8n8.x2.shared.b16 {%0,%1}, [%2];"
        : "=r"(r[0]), "=r"(r[1]) : "r"(addr));
}
__device__ __forceinline__ void mma16816(float* d, const uint32_t* a, const uint32_t* b) {
    asm volatile(
        "mma.sync.aligned.m16n8k16.row.col.f32.f16.f16.f32 "
        "{%0,%1,%2,%3}, {%4,%5,%6,%7}, {%8,%9}, {%0,%1,%2,%3};"
        : "+f"(d[0]), "+f"(d[1]), "+f"(d[2]), "+f"(d[3])
        : "r"(a[0]), "r"(a[1]), "r"(a[2]), "r"(a[3]), "r"(b[0]), "r"(b[1]));
}
__device__ __forceinline__ unsigned split_hi(float x, float y, float& lx, float& ly) {
    __half hx = __float2half_rn(x), hy = __float2half_rn(y);
    lx = x - __half2float(hx);
    ly = y - __half2float(hy);
    return pack2(hx, hy);
}
__device__ __forceinline__ void cpa16(uint32_t dst, const void* src) {
    asm volatile("cp.async.cg.shared.global [%0], [%1], 16;" :: "r"(dst), "l"(src));
}
#define CP_COMMIT() asm volatile("cp.async.commit_group;" ::: "memory")
#define CP_WAIT(n)  asm volatile("cp.async.wait_group %0;" :: "n"(n) : "memory")
#define SWZ8(row, ch)   (((row) * 128) + ((((ch) ^ ((row) & 7))) << 4))

// ============ conv X -> fp16 hi/lo ============
__global__ __launch_bounds__(256) void convx_kernel(const float* __restrict__ X)
{
    int c = blockIdx.x * 256 + threadIdx.x;
    float4 v = ((const float4*)X)[c];
    float lx, ly, lz, lw;
    uint2 h, l;
    h.x = split_hi(v.x, v.y, lx, ly);
    h.y = split_hi(v.z, v.w, lz, lw);
    l.x = pack2(__float2half_rn(lx), __float2half_rn(ly));
    l.y = pack2(__float2half_rn(lz), __float2half_rn(lw));
    ((uint2*)g_xh)[c] = h;
    ((uint2*)g_xl)[c] = l;
}

// ============ conv W (q,k,v) -> fp16 hi/lo ============
__global__ __launch_bounds__(256) void convw_kernel(
    const float* __restrict__ Wq, const float* __restrict__ Wk, const float* __restrict__ Wv)
{
    const int per = HID * HID / 4;
    int c = blockIdx.x * 256 + threadIdx.x;
    int z = c / per;
    const float* W = (z == 0) ? Wq : (z == 1) ? Wk : Wv;
    float4 v = ((const float4*)W)[c - z * per];
    float lx, ly, lz, lw;
    uint2 h, l;
    h.x = split_hi(v.x, v.y, lx, ly);
    h.y = split_hi(v.z, v.w, lz, lw);
    l.x = pack2(__float2half_rn(lx), __float2half_rn(ly));
    l.y = pack2(__float2half_rn(lz), __float2half_rn(lw));
    ((uint2*)g_wh)[c] = h;
    ((uint2*)g_wl)[c] = l;
}

// ============ proj via HMMA (fp16 3-pass): out = X @ W^T + b ============
#define PJ_XH 0
#define PJ_XL 16384
#define PJ_WH 32768
#define PJ_WL 40960
#define PJ_SMEM 49152

__global__ __launch_bounds__(256) void proj_mma_kernel(
    const float* __restrict__ bq, const float* __restrict__ bk, const float* __restrict__ bv)
{
    extern __shared__ char smem[];
    const uint32_t sbase = smem_to_u32(smem);
    const int otile = blockIdx.x, mtile = blockIdx.y, z = blockIdx.z;
    const float* bias = (z == 0) ? bq : (z == 1) ? bk : bv;
    const int tid = threadIdx.x, wid = tid >> 5, lane = tid & 31;
    const int m0 = wid * 16;
    const int rowA = m0 + (lane & 15);
    const int selA = lane >> 4;
    const int rowB8 = lane & 7;
    const int selB = (lane >> 3) & 1;
    const int c2 = 2 * (lane & 3);

    float fin[32];
#pragma unroll
    for (int e = 0; e < 32; e++) fin[e] = 0.f;

    for (int kc = 0; kc < HID / 64; kc++) {
        __syncthreads();
#pragma unroll
        for (int c = 0; c < 8; c++) {
            int idx = tid + 256 * c;
            int half = idx >> 10;
            int rem = idx & 1023;
            int row = rem >> 3, ch = rem & 7;
            const __half* src = (half ? g_xl : g_xh) +
                (size_t)(mtile * 128 + row) * HID + kc * 64 + ch * 8;
            *(uint4*)(smem + (half ? PJ_XL : PJ_XH) + SWZ8(row, ch)) = *(const uint4*)src;
        }
#pragma unroll
        for (int c = 0; c < 4; c++) {
            int idx = tid + 256 * c;
            int half = idx >> 9;
            int rem = idx & 511;
            int row = rem >> 3, ch = rem & 7;
            const __half* src = (half ? g_wl : g_wh) +
                ((size_t)z * HID + otile * 64 + row) * HID + kc * 64 + ch * 8;
            *(uint4*)(smem + (half ? PJ_WL : PJ_WH) + SWZ8(row, ch)) = *(const uint4*)src;
        }
        __syncthreads();

#pragma unroll
        for (int ks = 0; ks < 4; ks++) {
            uint32_t Ah[4], Al[4];
            ldsm_x4(Ah, sbase + PJ_XH + SWZ8(rowA, ks * 2 + selA));
            ldsm_x4(Al, sbase + PJ_XL + SWZ8(rowA, ks * 2 + selA));
#pragma unroll
            for (int nf = 0; nf < 8; nf++) {
                uint32_t Bh[2], Bl[2];
                ldsm_x2(Bh, sbase + PJ_WH + SWZ8(nf * 8 + rowB8, ks * 2 + selB));
                ldsm_x2(Bl, sbase + PJ_WL + SWZ8(nf * 8 + rowB8, ks * 2 + selB));
                mma16816(fin + nf * 4, Ah, Bh);
                mma16816(fin + nf * 4, Ah, Bl);
                mma16816(fin + nf * 4, Al, Bh);
            }
        }
    }

    const int ma = mtile * 128 + m0 + (lane >> 2);
    const int b = ma >> 11;
    const int sa = ma & (SQ - 1), sb = sa + 8;
    const int bn = b * NH + otile;
#pragma unroll
    for (int nf = 0; nf < 8; nf++) {
        int col = nf * 8 + c2;
        float bsx = bias[otile * 64 + col], bsy = bias[otile * 64 + col + 1];
        float a0 = fin[nf * 4 + 0] + bsx, a1 = fin[nf * 4 + 1] + bsy;
        float b0 = fin[nf * 4 + 2] + bsx, b1 = fin[nf * 4 + 3] + bsy;
        size_t offa = ((size_t)bn * SQ + sa) * DH + col;
        size_t offb = ((size_t)bn * SQ + sb) * DH + col;
        if (z == 2) {
            *(float2*)&g_v[offa] = make_float2(a0, a1);
            *(float2*)&g_v[offb] = make_float2(b0, b1);
        } else {
            __half* dh = (z == 0) ? g_qh : g_kh;
            *(unsigned*)&dh[offa] = pack2(__float2half_rn(a0), __float2half_rn(a1));
            *(unsigned*)&dh[offb] = pack2(__float2half_rn(b0), __float2half_rn(b1));
        }
    }
}

// ============ qb via HMMA (fp16 1-pass): q'_r = q @ bili[r,n] -> slot 1+r ============
#define QB_QH 0
#define QB_BH 16384
#define QB_SMEM 24576

__global__ __launch_bounds__(256) void qb_mma_kernel(const float* __restrict__ bili)
{
    extern __shared__ char smem[];
    const uint32_t sbase = smem_to_u32(smem);
    const int it = blockIdx.x, bn = blockIdx.y, r = blockIdx.z;
    const int n = bn % NH;
    const int tid = threadIdx.x, wid = tid >> 5, lane = tid & 31;
    const int m0 = wid * 16;
    const int rowA = m0 + (lane & 15);
    const int selA = lane >> 4;
    const int rowB8 = lane & 7;
    const int selB = (lane >> 3) & 1;
    const int c2 = 2 * (lane & 3);

    // q tile (slot 0 hi) 128x64 fp16 = 1024 uint4
#pragma unroll
    for (int c = 0; c < 4; c++) {
        int idx = tid + 256 * c;
        int row = idx >> 3, ch = idx & 7;
        const __half* src = g_qh + ((size_t)bn * SQ + it * 128 + row) * DH + ch * 8;
        *(uint4*)(smem + QB_QH + SWZ8(row, ch)) = *(const uint4*)src;
    }
    // bili[r][n] transposed, fp16 hi
    const float* bb = bili + ((size_t)r * NH + n) * DH * DH;
#pragma unroll
    for (int c = 0; c < 16; c++) {
        int id = tid + 256 * c;
        int p = id >> 6, t = id & 63;
        float v = bb[p * 64 + t];
        uint32_t byteoff = SWZ8(t, p >> 3) + (p & 7) * 2;
        *(__half*)(smem + QB_BH + byteoff) = __float2half_rn(v);
    }
    __syncthreads();

    float fin[32];
#pragma unroll
    for (int e = 0; e < 32; e++) fin[e] = 0.f;

#pragma unroll
    for (int ks = 0; ks < 4; ks++) {
        uint32_t Ah[4];
        ldsm_x4(Ah, sbase + QB_QH + SWZ8(rowA, ks * 2 + selA));
#pragma unroll
        for (int nf = 0; nf < 8; nf++) {
            uint32_t Bh[2];
            ldsm_x2(Bh, sbase + QB_BH + SWZ8(nf * 8 + rowB8, ks * 2 + selB));
            mma16816(fin + nf * 4, Ah, Bh);
        }
    }

    const int slot = 1 + r;
    const int ia = it * 128 + m0 + (lane >> 2);
    const int ib = ia + 8;
#pragma unroll
    for (int nf = 0; nf < 8; nf++) {
        int col = nf * 8 + c2;
        size_t offa = (((size_t)slot * BN + bn) * SQ + ia) * DH + col;
        size_t offb = (((size_t)slot * BN + bn) * SQ + ib) * DH + col;
        *(unsigned*)&g_qh[offa] = pack2(__float2half_rn(fin[nf * 4 + 0]), __float2half_rn(fin[nf * 4 + 1]));
        *(unsigned*)&g_qh[offb] = pack2(__float2half_rn(fin[nf * 4 + 2]), __float2half_rn(fin[nf * 4 + 3]));
    }
}

// ============ transpose+convert V -> g_vth/g_vtl [bn][d][s] (fp16 hi/lo) ============
__global__ __launch_bounds__(256) void vt_kernel()
{
    const int st = blockIdx.x, bn = blockIdx.y;
    __shared__ float tile[64][65];
    const int t = threadIdx.x;
#pragma unroll
    for (int c = 0; c < 4; c++) {
        int id = t + 256 * c, row = id >> 4, c4 = (id & 15) << 2;
        float4 v = *(const float4*)&g_v[((size_t)bn * SQ + st * 64 + row) * DH + c4];
        tile[row][c4 + 0] = v.x; tile[row][c4 + 1] = v.y;
        tile[row][c4 + 2] = v.z; tile[row][c4 + 3] = v.w;
    }
    __syncthreads();
#pragma unroll
    for (int c = 0; c < 4; c++) {
        int id = t + 256 * c, d = id >> 4, s4 = (id & 15) << 2;
        float f0 = tile[s4 + 0][d], f1 = tile[s4 + 1][d];
        float f2 = tile[s4 + 2][d], f3 = tile[s4 + 3][d];
        float l0, l1, l2, l3;
        uint2 hv, lv;
        hv.x = split_hi(f0, f1, l0, l1);
        hv.y = split_hi(f2, f3, l2, l3);
        lv.x = pack2(__float2half_rn(l0), __float2half_rn(l1));
        lv.y = pack2(__float2half_rn(l2), __float2half_rn(l3));
        size_t off = ((size_t)bn * DH + d) * SQ + st * 64 + s4;
        *(uint2*)&g_vth[off] = hv;
        *(uint2*)&g_vtl[off] = lv;
    }
}

// ============ pack adj -> bitmask [r][b][jword][i] ============
__global__ __launch_bounds__(256) void pack_kernel(const float* __restrict__ adj)
{
    const int jw = blockIdx.x, b = blockIdx.y, r = blockIdx.z;
#pragma unroll
    for (int ii = 0; ii < 8; ii++) {
        int i = threadIdx.x + 256 * ii;
        const float* src = adj + (((size_t)(r * BB + b)) * SQ + i) * SQ + jw * 32;
        unsigned bits = 0;
#pragma unroll
        for (int e8 = 0; e8 < 8; e8++) {
            float4 v = *(const float4*)(src + e8 * 4);
            bits |= (unsigned)(v.x != 0.f) << (e8 * 4 + 0);
            bits |= (unsigned)(v.y != 0.f) << (e8 * 4 + 1);
            bits |= (unsigned)(v.z != 0.f) << (e8 * 4 + 2);
            bits |= (unsigned)(v.w != 0.f) << (e8 * 4 + 3);
        }
        g_adjbits[((size_t)(r * BB + b) * 64 + jw) * SQ + i] = bits;
    }
}

// ============ fused flash (fp16, cp.async pipelined) ============
// grid (NH, SQ/64, BB), block 128. SMEM 72KB -> up to 3 CTAs/SM.
#define FQ(s)     ((s) * 8192)              // slots 0..5 hi
#define FKT       49152                     // K hi, 8KB
#define FVT(half) (57344 + (half) * 8192)   // V hi/lo, 16KB
#define FL_SMEM   73728

__global__ __launch_bounds__(128) void flash_kernel(
    const float* __restrict__ absb, const float* __restrict__ mask,
    float* __restrict__ out)
{
    extern __shared__ char smem[];
    const uint32_t sbase = smem_to_u32(smem);
    const int n = blockIdx.x, it = blockIdx.y, b = blockIdx.z;
    const int bn = b * NH + n;
    const int i0 = it * 64;
    const int tid = threadIdx.x, wid = tid >> 5, lane = tid & 31;
    const int m0 = wid * 16;

    auto load_k = [&](int jt) {
#pragma unroll
        for (int c = 0; c < 4; c++) {
            int idx = tid + 128 * c;
            int row = idx >> 3, ch = idx & 7;
            const __half* src = g_kh + ((size_t)bn * SQ + jt * 64 + row) * DH + ch * 8;
            cpa16(sbase + FKT + SWZ8(row, ch), src);
        }
        CP_COMMIT();
    };
    auto load_v = [&](int jt) {
#pragma unroll
        for (int c = 0; c < 8; c++) {
            int idx = tid + 128 * c;
            int half = idx >> 9;
            int rem = idx & 511;
            int row = rem >> 3, ch = rem & 7;
            const __half* src = (half ? g_vtl : g_vth) +
                ((size_t)bn * DH + row) * SQ + jt * 64 + ch * 8;
            cpa16(sbase + FVT(half) + SWZ8(row, ch), src);
        }
        CP_COMMIT();
    };

    load_k(0);
    load_v(0);

    // ---- load 6 Q tiles (64x64 fp16, swizzled): slots 0..5 hi ----
#pragma unroll
    for (int c = 0; c < 24; c++) {
        int idx = tid + 128 * c;
        int tile = idx >> 9;                // 0..5
        int rem = idx & 511;
        int row = rem >> 3, ch = rem & 7;
        const __half* src = g_qh +
            (((size_t)tile * BN + bn) * SQ + i0 + row) * DH + ch * 8;
        *(uint4*)(smem + FQ(tile) + SWZ8(row, ch)) = *(const uint4*)src;
    }

    const int rowA = m0 + (lane & 15);
    const int selA = lane >> 4;
    const int rowB8 = lane & 7;
    const int selB = (lane >> 3) & 1;
    const int c2 = 2 * (lane & 3);
    const int ia = i0 + m0 + (lane >> 2);
    const int ib = ia + 8;

    float ab[RR];
#pragma unroll
    for (int r = 0; r < RR; r++) ab[r] = absb[r * NH + n];
    const float* maskb = mask + b * SQ;

    float O[32];
#pragma unroll
    for (int e = 0; e < 32; e++) O[e] = 0.f;
    float mr[2] = {-1e30f, -1e30f};
    float lr[2] = {0.f, 0.f};

    for (int jt = 0; jt < 32; jt++) {
        CP_WAIT(1);                 // K(jt) ready (V(jt) may be in flight)
        __syncthreads();

        // ---- QK + structural bias ----
        float fin[32];
#pragma unroll
        for (int jh = 0; jh < 2; jh++) {
            uint32_t BK[4][4][2];
#pragma unroll
            for (int ks = 0; ks < 4; ks++)
#pragma unroll
                for (int nf = 0; nf < 4; nf++)
                    ldsm_x2(BK[ks][nf],
                            sbase + FKT + SWZ8(jh * 32 + nf * 8 + rowB8, ks * 2 + selB));

            const int jw = jt * 2 + jh;
            unsigned aw1[RR], aw2[RR];
#pragma unroll
            for (int r = 0; r < RR; r++) {
                aw1[r] = g_adjbits[((size_t)(r * BB + b) * 64 + jw) * SQ + ia];
                aw2[r] = g_adjbits[((size_t)(r * BB + b) * 64 + jw) * SQ + ib];
            }

            // slot 0: fp16 1-pass
            float facc[16] = {};
#pragma unroll
            for (int ks = 0; ks < 4; ks++) {
                uint32_t Ah[4];
                ldsm_x4(Ah, sbase + FQ(0) + SWZ8(rowA, ks * 2 + selA));
#pragma unroll
                for (int nf = 0; nf < 4; nf++)
                    mma16816(facc + nf * 4, Ah, BK[ks][nf]);
            }

            // slots 1..5: fp16 1-pass + bitmask combine
#pragma unroll
            for (int s = 1; s < 6; s++) {
                float tmp[16] = {};
#pragma unroll
                for (int ks = 0; ks < 4; ks++) {
                    uint32_t Ah[4];
                    ldsm_x4(Ah, sbase + FQ(s) + SWZ8(rowA, ks * 2 + selA));
#pragma unroll
                    for (int nf = 0; nf < 4; nf++)
                        mma16816(tmp + nf * 4, Ah, BK[ks][nf]);
                }
                const int r = s - 1;
                const float abr = ab[r];
#pragma unroll
                for (int nf = 0; nf < 4; nf++) {
                    int sh = nf * 8 + c2;
                    if ((aw1[r] >> sh) & 1)       facc[nf * 4 + 0] += tmp[nf * 4 + 0] + abr;
                    if ((aw1[r] >> (sh + 1)) & 1) facc[nf * 4 + 1] += tmp[nf * 4 + 1] + abr;
                    if ((aw2[r] >> sh) & 1)       facc[nf * 4 + 2] += tmp[nf * 4 + 2] + abr;
                    if ((aw2[r] >> (sh + 1)) & 1) facc[nf * 4 + 3] += tmp[nf * 4 + 3] + abr;
                }
            }
#pragma unroll
            for (int e = 0; e < 16; e++) fin[jh * 16 + e] = facc[e];
        }

        __syncthreads();            // K reads done
        if (jt < 31) load_k(jt + 1);

        // ---- scale + mask ----
#pragma unroll
        for (int q = 0; q < 8; q++) {
            int jh = q >> 2, nf = q & 3;
            float2 mk = __ldg((const float2*)&maskb[jt * 64 + jh * 32 + nf * 8 + c2]);
            fin[q * 4 + 0] = fin[q * 4 + 0] * 0.125f + mk.x;
            fin[q * 4 + 1] = fin[q * 4 + 1] * 0.125f + mk.y;
            fin[q * 4 + 2] = fin[q * 4 + 2] * 0.125f + mk.x;
            fin[q * 4 + 3] = fin[q * 4 + 3] * 0.125f + mk.y;
        }

        // ---- online softmax over 64 cols ----
        float mxa = -1e30f, mxb = -1e30f;
#pragma unroll
        for (int q = 0; q < 8; q++) {
            mxa = fmaxf(mxa, fmaxf(fin[q * 4 + 0], fin[q * 4 + 1]));
            mxb = fmaxf(mxb, fmaxf(fin[q * 4 + 2], fin[q * 4 + 3]));
        }
        mxa = fmaxf(mxa, __shfl_xor_sync(0xffffffffu, mxa, 1));
        mxa = fmaxf(mxa, __shfl_xor_sync(0xffffffffu, mxa, 2));
        mxb = fmaxf(mxb, __shfl_xor_sync(0xffffffffu, mxb, 1));
        mxb = fmaxf(mxb, __shfl_xor_sync(0xffffffffu, mxb, 2));
        float mna = fmaxf(mr[0], mxa), mnb = fmaxf(mr[1], mxb);
        float ala = __expf(mr[0] - mna), alb = __expf(mr[1] - mnb);
        mr[0] = mna; mr[1] = mnb;

        float sa = 0.f, sb = 0.f;
#pragma unroll
        for (int q = 0; q < 8; q++) {
            fin[q * 4 + 0] = __expf(fin[q * 4 + 0] - mna);
            fin[q * 4 + 1] = __expf(fin[q * 4 + 1] - mna);
            fin[q * 4 + 2] = __expf(fin[q * 4 + 2] - mnb);
            fin[q * 4 + 3] = __expf(fin[q * 4 + 3] - mnb);
            sa += fin[q * 4 + 0] + fin[q * 4 + 1];
            sb += fin[q * 4 + 2] + fin[q * 4 + 3];
        }
        sa += __shfl_xor_sync(0xffffffffu, sa, 1);
        sa += __shfl_xor_sync(0xffffffffu, sa, 2);
        sb += __shfl_xor_sync(0xffffffffu, sb, 1);
        sb += __shfl_xor_sync(0xffffffffu, sb, 2);
        lr[0] = lr[0] * ala + sa;
        lr[1] = lr[1] * alb + sb;

#pragma unroll
        for (int dn = 0; dn < 8; dn++) {
            O[dn * 4 + 0] *= ala; O[dn * 4 + 1] *= ala;
            O[dn * 4 + 2] *= alb; O[dn * 4 + 3] *= alb;
        }

        // ---- pack P fp16 hi/lo ----
        uint32_t Ph[4][4], Pl[4][4];
#pragma unroll
        for (int jk = 0; jk < 4; jk++) {
            int jh = jk >> 1, jj = jk & 1;
            int b0 = jh * 16 + (2 * jj) * 4;
            int b1 = jh * 16 + (2 * jj + 1) * 4;
            float l0, l1;
            Ph[jk][0] = split_hi(fin[b0 + 0], fin[b0 + 1], l0, l1);
            Pl[jk][0] = pack2(__float2half_rn(l0), __float2half_rn(l1));
            Ph[jk][1] = split_hi(fin[b0 + 2], fin[b0 + 3], l0, l1);
            Pl[jk][1] = pack2(__float2half_rn(l0), __float2half_rn(l1));
            Ph[jk][2] = split_hi(fin[b1 + 0], fin[b1 + 1], l0, l1);
            Pl[jk][2] = pack2(__float2half_rn(l0), __float2half_rn(l1));
            Ph[jk][3] = split_hi(fin[b1 + 2], fin[b1 + 3], l0, l1);
            Pl[jk][3] = pack2(__float2half_rn(l0), __float2half_rn(l1));
        }

        if (jt < 31) { CP_WAIT(1); } else { CP_WAIT(0); }   // V(jt) ready
        __syncthreads();

        // ---- P @ V (3-pass) ----
#pragma unroll
        for (int jk = 0; jk < 4; jk++) {
#pragma unroll
            for (int dn = 0; dn < 8; dn++) {
                uint32_t BVh[2], BVl[2];
                uint32_t vaddr = SWZ8(dn * 8 + rowB8, jk * 2 + selB);
                ldsm_x2(BVh, sbase + FVT(0) + vaddr);
                ldsm_x2(BVl, sbase + FVT(1) + vaddr);
                mma16816(O + dn * 4, Ph[jk], BVh);
                mma16816(O + dn * 4, Ph[jk], BVl);
                mma16816(O + dn * 4, Pl[jk], BVh);
            }
        }

        __syncthreads();            // V reads done
        if (jt < 31) load_v(jt + 1);
    }

    const float inva = 1.0f / lr[0], invb = 1.0f / lr[1];
#pragma unroll
    for (int dn = 0; dn < 8; dn++) {
        int d = dn * 8 + c2;
        float2 oa, ob;
        oa.x = O[dn * 4 + 0] * inva; oa.y = O[dn * 4 + 1] * inva;
        ob.x = O[dn * 4 + 2] * invb; ob.y = O[dn * 4 + 3] * invb;
        *(float2*)&out[((size_t)b * SQ + ia) * HID + n * 64 + d] = oa;
        *(float2*)&out[((size_t)b * SQ + ib) * HID + n * 64 + d] = ob;
    }
}

// =================================================================
extern "C" void kernel_launch(void* const* d_in, const int* in_sizes, int n_in,
                              void* d_out, int out_size)
{
    const float* hidden = (const float*)d_in[0];
    const float* mask   = (const float*)d_in[1];
    const float* adj    = (const float*)d_in[2];
    const float* Wq     = (const float*)d_in[3];
    const float* bq     = (const float*)d_in[4];
    const float* Wk     = (const float*)d_in[5];
    const float* bk     = (const float*)d_in[6];
    const float* Wv     = (const float*)d_in[7];
    const float* bv     = (const float*)d_in[8];
    const float* bili   = (const float*)d_in[9];
    const float* absb   = (const float*)d_in[10];
    float* out = (float*)d_out;
    (void)in_sizes; (void)n_in; (void)out_size;

    cudaFuncSetAttribute(proj_mma_kernel, cudaFuncAttributeMaxDynamicSharedMemorySize, PJ_SMEM);
    cudaFuncSetAttribute(qb_mma_kernel, cudaFuncAttributeMaxDynamicSharedMemorySize, QB_SMEM);
    cudaFuncSetAttribute(flash_kernel, cudaFuncAttributeMaxDynamicSharedMemorySize, FL_SMEM);

    convx_kernel<<<BB * SQ * HID / 4 / 256, 256>>>(hidden);
    convw_kernel<<<3 * HID * HID / 4 / 256, 256>>>(Wq, Wk, Wv);
    proj_mma_kernel<<<dim3(HID / 64, BB * SQ / 128, 3), 256, PJ_SMEM>>>(bq, bk, bv);
    qb_mma_kernel<<<dim3(SQ / 128, BN, RR), 256, QB_SMEM>>>(bili);
    vt_kernel<<<dim3(SQ / 64, BN), 256>>>();
    pack_kernel<<<dim3(SQ / 32, BB, RR), 256>>>(adj);
    flash_kernel<<<dim3(NH, SQ / 64, BB), 128, FL_SMEM>>>(absb, mask, out);
}

// round 16
// speedup vs baseline: 1.3592x; 1.0713x over previous
#include <cuda_runtime.h>
#include <cuda_fp16.h>
#include <cstdint>
#include <math.h>

#define SQ   2048
#define HID  768
#define BB   2
#define NH   12
#define DH   64
#define RR   5
#define BN   24

// ---------------- device scratch ----------------
__device__ float g_v   [(size_t)BN * SQ * DH];
__device__ __half g_xh[(size_t)BB * SQ * HID];
__device__ __half g_xl[(size_t)BB * SQ * HID];
__device__ __half g_wh[(size_t)3 * HID * HID];
__device__ __half g_wl[(size_t)3 * HID * HID];
__device__ __half g_qh[(size_t)6 * BN * SQ * DH];   // slots 0..5, fp16
__device__ __half g_kh[(size_t)BN * SQ * DH];
__device__ __half g_vth[(size_t)BN * DH * SQ];      // V^T [bn][d][s] fp16
__device__ unsigned g_adjbits[(size_t)RR * BB * (SQ / 32) * SQ];

// ================= helpers =================
__device__ __forceinline__ uint32_t smem_to_u32(const void* p) {
    uint32_t a;
    asm("{ .reg .u64 t; cvta.to.shared.u64 t, %1; cvt.u32.u64 %0, t; }" : "=r"(a) : "l"(p));
    return a;
}
__device__ __forceinline__ unsigned pack2(__half a, __half b) {
    __half2 t; t.x = a; t.y = b;
    return *reinterpret_cast<unsigned*>(&t);
}
__device__ __forceinline__ void ldsm_x4(uint32_t* r, uint32_t addr) {
    asm volatile("ldmatrix.sync.aligned.m8n8.x4.shared.b16 {%0,%1,%2,%3}, [%4];"
        : "=r"(r[0]), "=r"(r[1]), "=r"(r[2]), "=r"(r[3]) : "r"(addr));
}
__device__ __forceinline__ void ldsm_x2(uint32_t* r, uint32_t addr) {
    asm volatile("ldmatrix.sync.aligned.m8n8.x2.shared.b16 {%0,%1}, [%2];"
        : "=r"(r[0]), "=r"(r[1]) : "r"(addr));
}
__device__ __forceinline__ void mma16816(float* d, const uint32_t* a, const uint32_t* b) {
    asm volatile(
        "mma.sync.aligned.m16n8k16.row.col.f32.f16.f16.f32 "
        "{%0,%1,%2,%3}, {%4,%5,%6,%7}, {%8,%9}, {%0,%1,%2,%3};"
        : "+f"(d[0]), "+f"(d[1]), "+f"(d[2]), "+f"(d[3])
        : "r"(a[0]), "r"(a[1]), "r"(a[2]), "r"(a[3]), "r"(b[0]), "r"(b[1]));
}
__device__ __forceinline__ unsigned split_hi(float x, float y, float& lx, float& ly) {
    __half hx = __float2half_rn(x), hy = __float2half_rn(y);
    lx = x - __half2float(hx);
    ly = y - __half2float(hy);
    return pack2(hx, hy);
}
__device__ __forceinline__ void cpa16(uint32_t dst, const void* src) {
    asm volatile("cp.async.cg.shared.global [%0], [%1], 16;" :: "r"(dst), "l"(src));
}
#define CP_COMMIT() asm volatile("cp.async.commit_group;" ::: "memory")
#define CP_WAIT(n)  asm volatile("cp.async.wait_group %0;" :: "n"(n) : "memory")
#define SWZ8(row, ch)   (((row) * 128) + ((((ch) ^ ((row) & 7))) << 4))

// ============ conv X -> fp16 hi/lo ============
__global__ __launch_bounds__(256) void convx_kernel(const float* __restrict__ X)
{
    int c = blockIdx.x * 256 + threadIdx.x;
    float4 v = ((const float4*)X)[c];
    float lx, ly, lz, lw;
    uint2 h, l;
    h.x = split_hi(v.x, v.y, lx, ly);
    h.y = split_hi(v.z, v.w, lz, lw);
    l.x = pack2(__float2half_rn(lx), __float2half_rn(ly));
    l.y = pack2(__float2half_rn(lz), __float2half_rn(lw));
    ((uint2*)g_xh)[c] = h;
    ((uint2*)g_xl)[c] = l;
}

// ============ conv W (q,k,v) -> fp16 hi/lo ============
__global__ __launch_bounds__(256) void convw_kernel(
    const float* __restrict__ Wq, const float* __restrict__ Wk, const float* __restrict__ Wv)
{
    const int per = HID * HID / 4;
    int c = blockIdx.x * 256 + threadIdx.x;
    int z = c / per;
    const float* W = (z == 0) ? Wq : (z == 1) ? Wk : Wv;
    float4 v = ((const float4*)W)[c - z * per];
    float lx, ly, lz, lw;
    uint2 h, l;
    h.x = split_hi(v.x, v.y, lx, ly);
    h.y = split_hi(v.z, v.w, lz, lw);
    l.x = pack2(__float2half_rn(lx), __float2half_rn(ly));
    l.y = pack2(__float2half_rn(lz), __float2half_rn(lw));
    ((uint2*)g_wh)[c] = h;
    ((uint2*)g_wl)[c] = l;
}

// ============ proj via HMMA: out = X @ W^T + b ============
// z<2 (Q,K): 2-pass (Ah*Bh + Ah*Bl). z==2 (V): 3-pass (+ Al*Bh).
#define PJ_XH 0
#define PJ_XL 16384
#define PJ_WH 32768
#define PJ_WL 40960
#define PJ_SMEM 49152

__global__ __launch_bounds__(256) void proj_mma_kernel(
    const float* __restrict__ bq, const float* __restrict__ bk, const float* __restrict__ bv)
{
    extern __shared__ char smem[];
    const uint32_t sbase = smem_to_u32(smem);
    const int otile = blockIdx.x, mtile = blockIdx.y, z = blockIdx.z;
    const float* bias = (z == 0) ? bq : (z == 1) ? bk : bv;
    const int tid = threadIdx.x, wid = tid >> 5, lane = tid & 31;
    const int m0 = wid * 16;
    const int rowA = m0 + (lane & 15);
    const int selA = lane >> 4;
    const int rowB8 = lane & 7;
    const int selB = (lane >> 3) & 1;
    const int c2 = 2 * (lane & 3);

    float fin[32];
#pragma unroll
    for (int e = 0; e < 32; e++) fin[e] = 0.f;

    for (int kc = 0; kc < HID / 64; kc++) {
        __syncthreads();
#pragma unroll
        for (int c = 0; c < 8; c++) {
            int idx = tid + 256 * c;
            int half = idx >> 10;
            int rem = idx & 1023;
            int row = rem >> 3, ch = rem & 7;
            const __half* src = (half ? g_xl : g_xh) +
                (size_t)(mtile * 128 + row) * HID + kc * 64 + ch * 8;
            *(uint4*)(smem + (half ? PJ_XL : PJ_XH) + SWZ8(row, ch)) = *(const uint4*)src;
        }
#pragma unroll
        for (int c = 0; c < 4; c++) {
            int idx = tid + 256 * c;
            int half = idx >> 9;
            int rem = idx & 511;
            int row = rem >> 3, ch = rem & 7;
            const __half* src = (half ? g_wl : g_wh) +
                ((size_t)z * HID + otile * 64 + row) * HID + kc * 64 + ch * 8;
            *(uint4*)(smem + (half ? PJ_WL : PJ_WH) + SWZ8(row, ch)) = *(const uint4*)src;
        }
        __syncthreads();

#pragma unroll
        for (int ks = 0; ks < 4; ks++) {
            uint32_t Ah[4], Al[4];
            ldsm_x4(Ah, sbase + PJ_XH + SWZ8(rowA, ks * 2 + selA));
            if (z == 2) ldsm_x4(Al, sbase + PJ_XL + SWZ8(rowA, ks * 2 + selA));
#pragma unroll
            for (int nf = 0; nf < 8; nf++) {
                uint32_t Bh[2], Bl[2];
                ldsm_x2(Bh, sbase + PJ_WH + SWZ8(nf * 8 + rowB8, ks * 2 + selB));
                ldsm_x2(Bl, sbase + PJ_WL + SWZ8(nf * 8 + rowB8, ks * 2 + selB));
                mma16816(fin + nf * 4, Ah, Bh);
                mma16816(fin + nf * 4, Ah, Bl);
                if (z == 2) mma16816(fin + nf * 4, Al, Bh);
            }
        }
    }

    const int ma = mtile * 128 + m0 + (lane >> 2);
    const int b = ma >> 11;
    const int sa = ma & (SQ - 1), sb = sa + 8;
    const int bn = b * NH + otile;
#pragma unroll
    for (int nf = 0; nf < 8; nf++) {
        int col = nf * 8 + c2;
        float bsx = bias[otile * 64 + col], bsy = bias[otile * 64 + col + 1];
        float a0 = fin[nf * 4 + 0] + bsx, a1 = fin[nf * 4 + 1] + bsy;
        float b0 = fin[nf * 4 + 2] + bsx, b1 = fin[nf * 4 + 3] + bsy;
        size_t offa = ((size_t)bn * SQ + sa) * DH + col;
        size_t offb = ((size_t)bn * SQ + sb) * DH + col;
        if (z == 2) {
            *(float2*)&g_v[offa] = make_float2(a0, a1);
            *(float2*)&g_v[offb] = make_float2(b0, b1);
        } else {
            __half* dh = (z == 0) ? g_qh : g_kh;
            *(unsigned*)&dh[offa] = pack2(__float2half_rn(a0), __float2half_rn(a1));
            *(unsigned*)&dh[offb] = pack2(__float2half_rn(b0), __float2half_rn(b1));
        }
    }
}

// ============ qb via HMMA (fp16 1-pass): q'_r = q @ bili[r,n] -> slot 1+r ============
#define QB_QH 0
#define QB_BH 16384
#define QB_SMEM 24576

__global__ __launch_bounds__(256) void qb_mma_kernel(const float* __restrict__ bili)
{
    extern __shared__ char smem[];
    const uint32_t sbase = smem_to_u32(smem);
    const int it = blockIdx.x, bn = blockIdx.y, r = blockIdx.z;
    const int n = bn % NH;
    const int tid = threadIdx.x, wid = tid >> 5, lane = tid & 31;
    const int m0 = wid * 16;
    const int rowA = m0 + (lane & 15);
    const int selA = lane >> 4;
    const int rowB8 = lane & 7;
    const int selB = (lane >> 3) & 1;
    const int c2 = 2 * (lane & 3);

#pragma unroll
    for (int c = 0; c < 4; c++) {
        int idx = tid + 256 * c;
        int row = idx >> 3, ch = idx & 7;
        const __half* src = g_qh + ((size_t)bn * SQ + it * 128 + row) * DH + ch * 8;
        *(uint4*)(smem + QB_QH + SWZ8(row, ch)) = *(const uint4*)src;
    }
    const float* bb = bili + ((size_t)r * NH + n) * DH * DH;
#pragma unroll
    for (int c = 0; c < 16; c++) {
        int id = tid + 256 * c;
        int p = id >> 6, t = id & 63;
        float v = bb[p * 64 + t];
        uint32_t byteoff = SWZ8(t, p >> 3) + (p & 7) * 2;
        *(__half*)(smem + QB_BH + byteoff) = __float2half_rn(v);
    }
    __syncthreads();

    float fin[32];
#pragma unroll
    for (int e = 0; e < 32; e++) fin[e] = 0.f;

#pragma unroll
    for (int ks = 0; ks < 4; ks++) {
        uint32_t Ah[4];
        ldsm_x4(Ah, sbase + QB_QH + SWZ8(rowA, ks * 2 + selA));
#pragma unroll
        for (int nf = 0; nf < 8; nf++) {
            uint32_t Bh[2];
            ldsm_x2(Bh, sbase + QB_BH + SWZ8(nf * 8 + rowB8, ks * 2 + selB));
            mma16816(fin + nf * 4, Ah, Bh);
        }
    }

    const int slot = 1 + r;
    const int ia = it * 128 + m0 + (lane >> 2);
    const int ib = ia + 8;
#pragma unroll
    for (int nf = 0; nf < 8; nf++) {
        int col = nf * 8 + c2;
        size_t offa = (((size_t)slot * BN + bn) * SQ + ia) * DH + col;
        size_t offb = (((size_t)slot * BN + bn) * SQ + ib) * DH + col;
        *(unsigned*)&g_qh[offa] = pack2(__float2half_rn(fin[nf * 4 + 0]), __float2half_rn(fin[nf * 4 + 1]));
        *(unsigned*)&g_qh[offb] = pack2(__float2half_rn(fin[nf * 4 + 2]), __float2half_rn(fin[nf * 4 + 3]));
    }
}

// ============ transpose+convert V -> g_vth [bn][d][s] (fp16) ============
__global__ __launch_bounds__(256) void vt_kernel()
{
    const int st = blockIdx.x, bn = blockIdx.y;
    __shared__ float tile[64][65];
    const int t = threadIdx.x;
#pragma unroll
    for (int c = 0; c < 4; c++) {
        int id = t + 256 * c, row = id >> 4, c4 = (id & 15) << 2;
        float4 v = *(const float4*)&g_v[((size_t)bn * SQ + st * 64 + row) * DH + c4];
        tile[row][c4 + 0] = v.x; tile[row][c4 + 1] = v.y;
        tile[row][c4 + 2] = v.z; tile[row][c4 + 3] = v.w;
    }
    __syncthreads();
#pragma unroll
    for (int c = 0; c < 4; c++) {
        int id = t + 256 * c, d = id >> 4, s4 = (id & 15) << 2;
        uint2 hv;
        hv.x = pack2(__float2half_rn(tile[s4 + 0][d]), __float2half_rn(tile[s4 + 1][d]));
        hv.y = pack2(__float2half_rn(tile[s4 + 2][d]), __float2half_rn(tile[s4 + 3][d]));
        size_t off = ((size_t)bn * DH + d) * SQ + st * 64 + s4;
        *(uint2*)&g_vth[off] = hv;
    }
}

// ============ pack adj -> bitmask [r][b][jword][i] ============
__global__ __launch_bounds__(256) void pack_kernel(const float* __restrict__ adj)
{
    const int jw = blockIdx.x, b = blockIdx.y, r = blockIdx.z;
#pragma unroll
    for (int ii = 0; ii < 8; ii++) {
        int i = threadIdx.x + 256 * ii;
        const float* src = adj + (((size_t)(r * BB + b)) * SQ + i) * SQ + jw * 32;
        unsigned bits = 0;
#pragma unroll
        for (int e8 = 0; e8 < 8; e8++) {
            float4 v = *(const float4*)(src + e8 * 4);
            bits |= (unsigned)(v.x != 0.f) << (e8 * 4 + 0);
            bits |= (unsigned)(v.y != 0.f) << (e8 * 4 + 1);
            bits |= (unsigned)(v.z != 0.f) << (e8 * 4 + 2);
            bits |= (unsigned)(v.w != 0.f) << (e8 * 4 + 3);
        }
        g_adjbits[((size_t)(r * BB + b) * 64 + jw) * SQ + i] = bits;
    }
}

// ============ fused flash (fp16, cp.async pipelined) ============
// grid (NH, SQ/64, BB), block 128. SMEM 64KB.
#define FQ(s)     ((s) * 8192)              // slots 0..5
#define FKT       49152                     // K, 8KB
#define FVT       57344                     // V^T, 8KB
#define FL_SMEM   65536

__global__ __launch_bounds__(128) void flash_kernel(
    const float* __restrict__ absb, const float* __restrict__ mask,
    float* __restrict__ out)
{
    extern __shared__ char smem[];
    const uint32_t sbase = smem_to_u32(smem);
    const int n = blockIdx.x, it = blockIdx.y, b = blockIdx.z;
    const int bn = b * NH + n;
    const int i0 = it * 64;
    const int tid = threadIdx.x, wid = tid >> 5, lane = tid & 31;
    const int m0 = wid * 16;

    auto load_k = [&](int jt) {
#pragma unroll
        for (int c = 0; c < 4; c++) {
            int idx = tid + 128 * c;
            int row = idx >> 3, ch = idx & 7;
            const __half* src = g_kh + ((size_t)bn * SQ + jt * 64 + row) * DH + ch * 8;
            cpa16(sbase + FKT + SWZ8(row, ch), src);
        }
        CP_COMMIT();
    };
    auto load_v = [&](int jt) {
#pragma unroll
        for (int c = 0; c < 4; c++) {
            int idx = tid + 128 * c;
            int row = idx >> 3, ch = idx & 7;
            const __half* src = g_vth + ((size_t)bn * DH + row) * SQ + jt * 64 + ch * 8;
            cpa16(sbase + FVT + SWZ8(row, ch), src);
        }
        CP_COMMIT();
    };

    load_k(0);
    load_v(0);

    // ---- load 6 Q tiles (64x64 fp16, swizzled) ----
#pragma unroll
    for (int c = 0; c < 24; c++) {
        int idx = tid + 128 * c;
        int tile = idx >> 9;
        int rem = idx & 511;
        int row = rem >> 3, ch = rem & 7;
        const __half* src = g_qh +
            (((size_t)tile * BN + bn) * SQ + i0 + row) * DH + ch * 8;
        *(uint4*)(smem + FQ(tile) + SWZ8(row, ch)) = *(const uint4*)src;
    }

    const int rowA = m0 + (lane & 15);
    const int selA = lane >> 4;
    const int rowB8 = lane & 7;
    const int selB = (lane >> 3) & 1;
    const int c2 = 2 * (lane & 3);
    const int ia = i0 + m0 + (lane >> 2);
    const int ib = ia + 8;

    float ab[RR];
#pragma unroll
    for (int r = 0; r < RR; r++) ab[r] = absb[r * NH + n];
    const float* maskb = mask + b * SQ;

    float O[32];
#pragma unroll
    for (int e = 0; e < 32; e++) O[e] = 0.f;
    float mr[2] = {-1e30f, -1e30f};
    float lr[2] = {0.f, 0.f};

    for (int jt = 0; jt < 32; jt++) {
        CP_WAIT(1);                 // K(jt) ready
        __syncthreads();

        // ---- QK + structural bias ----
        float fin[32];
#pragma unroll
        for (int jh = 0; jh < 2; jh++) {
            uint32_t BK[4][4][2];
#pragma unroll
            for (int ks = 0; ks < 4; ks++)
#pragma unroll
                for (int nf = 0; nf < 4; nf++)
                    ldsm_x2(BK[ks][nf],
                            sbase + FKT + SWZ8(jh * 32 + nf * 8 + rowB8, ks * 2 + selB));

            const int jw = jt * 2 + jh;
            unsigned aw1[RR], aw2[RR];
#pragma unroll
            for (int r = 0; r < RR; r++) {
                aw1[r] = g_adjbits[((size_t)(r * BB + b) * 64 + jw) * SQ + ia];
                aw2[r] = g_adjbits[((size_t)(r * BB + b) * 64 + jw) * SQ + ib];
            }

            float facc[16] = {};
#pragma unroll
            for (int ks = 0; ks < 4; ks++) {
                uint32_t Ah[4];
                ldsm_x4(Ah, sbase + FQ(0) + SWZ8(rowA, ks * 2 + selA));
#pragma unroll
                for (int nf = 0; nf < 4; nf++)
                    mma16816(facc + nf * 4, Ah, BK[ks][nf]);
            }

#pragma unroll
            for (int s = 1; s < 6; s++) {
                float tmp[16] = {};
#pragma unroll
                for (int ks = 0; ks < 4; ks++) {
                    uint32_t Ah[4];
                    ldsm_x4(Ah, sbase + FQ(s) + SWZ8(rowA, ks * 2 + selA));
#pragma unroll
                    for (int nf = 0; nf < 4; nf++)
                        mma16816(tmp + nf * 4, Ah, BK[ks][nf]);
                }
                const int r = s - 1;
                const float abr = ab[r];
#pragma unroll
                for (int nf = 0; nf < 4; nf++) {
                    int sh = nf * 8 + c2;
                    if ((aw1[r] >> sh) & 1)       facc[nf * 4 + 0] += tmp[nf * 4 + 0] + abr;
                    if ((aw1[r] >> (sh + 1)) & 1) facc[nf * 4 + 1] += tmp[nf * 4 + 1] + abr;
                    if ((aw2[r] >> sh) & 1)       facc[nf * 4 + 2] += tmp[nf * 4 + 2] + abr;
                    if ((aw2[r] >> (sh + 1)) & 1) facc[nf * 4 + 3] += tmp[nf * 4 + 3] + abr;
                }
            }
#pragma unroll
            for (int e = 0; e < 16; e++) fin[jh * 16 + e] = facc[e];
        }

        __syncthreads();            // K reads done
        if (jt < 31) load_k(jt + 1);

        // ---- scale + mask ----
#pragma unroll
        for (int q = 0; q < 8; q++) {
            int jh = q >> 2, nf = q & 3;
            float2 mk = __ldg((const float2*)&maskb[jt * 64 + jh * 32 + nf * 8 + c2]);
            fin[q * 4 + 0] = fin[q * 4 + 0] * 0.125f + mk.x;
            fin[q * 4 + 1] = fin[q * 4 + 1] * 0.125f + mk.y;
            fin[q * 4 + 2] = fin[q * 4 + 2] * 0.125f + mk.x;
            fin[q * 4 + 3] = fin[q * 4 + 3] * 0.125f + mk.y;
        }

        // ---- online softmax over 64 cols ----
        float mxa = -1e30f, mxb = -1e30f;
#pragma unroll
        for (int q = 0; q < 8; q++) {
            mxa = fmaxf(mxa, fmaxf(fin[q * 4 + 0], fin[q * 4 + 1]));
            mxb = fmaxf(mxb, fmaxf(fin[q * 4 + 2], fin[q * 4 + 3]));
        }
        mxa = fmaxf(mxa, __shfl_xor_sync(0xffffffffu, mxa, 1));
        mxa = fmaxf(mxa, __shfl_xor_sync(0xffffffffu, mxa, 2));
        mxb = fmaxf(mxb, __shfl_xor_sync(0xffffffffu, mxb, 1));
        mxb = fmaxf(mxb, __shfl_xor_sync(0xffffffffu, mxb, 2));
        float mna = fmaxf(mr[0], mxa), mnb = fmaxf(mr[1], mxb);
        float ala = __expf(mr[0] - mna), alb = __expf(mr[1] - mnb);
        mr[0] = mna; mr[1] = mnb;

        float sa = 0.f, sb = 0.f;
#pragma unroll
        for (int q = 0; q < 8; q++) {
            fin[q * 4 + 0] = __expf(fin[q * 4 + 0] - mna);
            fin[q * 4 + 1] = __expf(fin[q * 4 + 1] - mna);
            fin[q * 4 + 2] = __expf(fin[q * 4 + 2] - mnb);
            fin[q * 4 + 3] = __expf(fin[q * 4 + 3] - mnb);
            sa += fin[q * 4 + 0] + fin[q * 4 + 1];
            sb += fin[q * 4 + 2] + fin[q * 4 + 3];
        }
        sa += __shfl_xor_sync(0xffffffffu, sa, 1);
        sa += __shfl_xor_sync(0xffffffffu, sa, 2);
        sb += __shfl_xor_sync(0xffffffffu, sb, 1);
        sb += __shfl_xor_sync(0xffffffffu, sb, 2);
        lr[0] = lr[0] * ala + sa;
        lr[1] = lr[1] * alb + sb;

#pragma unroll
        for (int dn = 0; dn < 8; dn++) {
            O[dn * 4 + 0] *= ala; O[dn * 4 + 1] *= ala;
            O[dn * 4 + 2] *= alb; O[dn * 4 + 3] *= alb;
        }

        // ---- pack P fp16 hi/lo ----
        uint32_t Ph[4][4], Pl[4][4];
#pragma unroll
        for (int jk = 0; jk < 4; jk++) {
            int jh = jk >> 1, jj = jk & 1;
            int b0 = jh * 16 + (2 * jj) * 4;
            int b1 = jh * 16 + (2 * jj + 1) * 4;
            float l0, l1;
            Ph[jk][0] = split_hi(fin[b0 + 0], fin[b0 + 1], l0, l1);
            Pl[jk][0] = pack2(__float2half_rn(l0), __float2half_rn(l1));
            Ph[jk][1] = split_hi(fin[b0 + 2], fin[b0 + 3], l0, l1);
            Pl[jk][1] = pack2(__float2half_rn(l0), __float2half_rn(l1));
            Ph[jk][2] = split_hi(fin[b1 + 0], fin[b1 + 1], l0, l1);
            Pl[jk][2] = pack2(__float2half_rn(l0), __float2half_rn(l1));
            Ph[jk][3] = split_hi(fin[b1 + 2], fin[b1 + 3], l0, l1);
            Pl[jk][3] = pack2(__float2half_rn(l0), __float2half_rn(l1));
        }

        if (jt < 31) { CP_WAIT(1); } else { CP_WAIT(0); }   // V(jt) ready
        __syncthreads();

        // ---- P @ V (2-pass: (Ph+Pl)*Vh) ----
#pragma unroll
        for (int jk = 0; jk < 4; jk++) {
#pragma unroll
            for (int dn = 0; dn < 8; dn++) {
                uint32_t BVh[2];
                ldsm_x2(BVh, sbase + FVT + SWZ8(dn * 8 + rowB8, jk * 2 + selB));
                mma16816(O + dn * 4, Ph[jk], BVh);
                mma16816(O + dn * 4, Pl[jk], BVh);
            }
        }

        __syncthreads();            // V reads done
        if (jt < 31) load_v(jt + 1);
    }

    const float inva = 1.0f / lr[0], invb = 1.0f / lr[1];
#pragma unroll
    for (int dn = 0; dn < 8; dn++) {
        int d = dn * 8 + c2;
        float2 oa, ob;
        oa.x = O[dn * 4 + 0] * inva; oa.y = O[dn * 4 + 1] * inva;
        ob.x = O[dn * 4 + 2] * invb; ob.y = O[dn * 4 + 3] * invb;
        *(float2*)&out[((size_t)b * SQ + ia) * HID + n * 64 + d] = oa;
        *(float2*)&out[((size_t)b * SQ + ib) * HID + n * 64 + d] = ob;
    }
}

// =================================================================
extern "C" void kernel_launch(void* const* d_in, const int* in_sizes, int n_in,
                              void* d_out, int out_size)
{
    const float* hidden = (const float*)d_in[0];
    const float* mask   = (const float*)d_in[1];
    const float* adj    = (const float*)d_in[2];
    const float* Wq     = (const float*)d_in[3];
    const float* bq     = (const float*)d_in[4];
    const float* Wk     = (const float*)d_in[5];
    const float* bk     = (const float*)d_in[6];
    const float* Wv     = (const float*)d_in[7];
    const float* bv     = (const float*)d_in[8];
    const float* bili   = (const float*)d_in[9];
    const float* absb   = (const float*)d_in[10];
    float* out = (float*)d_out;
    (void)in_sizes; (void)n_in; (void)out_size;

    cudaFuncSetAttribute(proj_mma_kernel, cudaFuncAttributeMaxDynamicSharedMemorySize, PJ_SMEM);
    cudaFuncSetAttribute(qb_mma_kernel, cudaFuncAttributeMaxDynamicSharedMemorySize, QB_SMEM);
    cudaFuncSetAttribute(flash_kernel, cudaFuncAttributeMaxDynamicSharedMemorySize, FL_SMEM);

    convx_kernel<<<BB * SQ * HID / 4 / 256, 256>>>(hidden);
    convw_kernel<<<3 * HID * HID / 4 / 256, 256>>>(Wq, Wk, Wv);
    proj_mma_kernel<<<dim3(HID / 64, BB * SQ / 128, 3), 256, PJ_SMEM>>>(bq, bk, bv);
    qb_mma_kernel<<<dim3(SQ / 128, BN, RR), 256, QB_SMEM>>>(bili);
    vt_kernel<<<dim3(SQ / 64, BN), 256>>>();
    pack_kernel<<<dim3(SQ / 32, BB, RR), 256>>>(adj);
    flash_kernel<<<dim3(NH, SQ / 64, BB), 128, FL_SMEM>>>(absb, mask, out);
}

// round 17
// speedup vs baseline: 1.4507x; 1.0673x over previous
#include <cuda_runtime.h>
#include <cuda_fp16.h>
#include <cstdint>
#include <math.h>

#define SQ   2048
#define HID  768
#define BB   2
#define NH   12
#define DH   64
#define RR   5
#define BN   24

// ---------------- device scratch ----------------
__device__ float g_v   [(size_t)BN * SQ * DH];
__device__ __half g_xh[(size_t)BB * SQ * HID];
__device__ __half g_xl[(size_t)BB * SQ * HID];
__device__ __half g_wh[(size_t)3 * HID * HID];
__device__ __half g_wl[(size_t)3 * HID * HID];
__device__ __half g_qh[(size_t)6 * BN * SQ * DH];   // slots 0..5, fp16
__device__ __half g_kh[(size_t)BN * SQ * DH];
__device__ __half g_vth[(size_t)BN * DH * SQ];      // V^T [bn][d][s] fp16
__device__ unsigned g_adjbits[(size_t)RR * BB * (SQ / 32) * SQ];

// ================= helpers =================
__device__ __forceinline__ uint32_t smem_to_u32(const void* p) {
    uint32_t a;
    asm("{ .reg .u64 t; cvta.to.shared.u64 t, %1; cvt.u32.u64 %0, t; }" : "=r"(a) : "l"(p));
    return a;
}
__device__ __forceinline__ unsigned pack2(__half a, __half b) {
    __half2 t; t.x = a; t.y = b;
    return *reinterpret_cast<unsigned*>(&t);
}
__device__ __forceinline__ void ldsm_x4(uint32_t* r, uint32_t addr) {
    asm volatile("ldmatrix.sync.aligned.m8n8.x4.shared.b16 {%0,%1,%2,%3}, [%4];"
        : "=r"(r[0]), "=r"(r[1]), "=r"(r[2]), "=r"(r[3]) : "r"(addr));
}
__device__ __forceinline__ void ldsm_x2(uint32_t* r, uint32_t addr) {
    asm volatile("ldmatrix.sync.aligned.m8n8.x2.shared.b16 {%0,%1}, [%2];"
        : "=r"(r[0]), "=r"(r[1]) : "r"(addr));
}
__device__ __forceinline__ void mma16816(float* d, const uint32_t* a, const uint32_t* b) {
    asm volatile(
        "mma.sync.aligned.m16n8k16.row.col.f32.f16.f16.f32 "
        "{%0,%1,%2,%3}, {%4,%5,%6,%7}, {%8,%9}, {%0,%1,%2,%3};"
        : "+f"(d[0]), "+f"(d[1]), "+f"(d[2]), "+f"(d[3])
        : "r"(a[0]), "r"(a[1]), "r"(a[2]), "r"(a[3]), "r"(b[0]), "r"(b[1]));
}
__device__ __forceinline__ unsigned split_hi(float x, float y, float& lx, float& ly) {
    __half hx = __float2half_rn(x), hy = __float2half_rn(y);
    lx = x - __half2float(hx);
    ly = y - __half2float(hy);
    return pack2(hx, hy);
}
__device__ __forceinline__ void cpa16(uint32_t dst, const void* src) {
    asm volatile("cp.async.cg.shared.global [%0], [%1], 16;" :: "r"(dst), "l"(src));
}
#define CP_COMMIT() asm volatile("cp.async.commit_group;" ::: "memory")
#define CP_WAIT(n)  asm volatile("cp.async.wait_group %0;" :: "n"(n) : "memory")
#define SWZ8(row, ch)   (((row) * 128) + ((((ch) ^ ((row) & 7))) << 4))

// ============ conv X -> fp16 hi/lo ============
__global__ __launch_bounds__(256) void convx_kernel(const float* __restrict__ X)
{
    int c = blockIdx.x * 256 + threadIdx.x;
    float4 v = ((const float4*)X)[c];
    float lx, ly, lz, lw;
    uint2 h, l;
    h.x = split_hi(v.x, v.y, lx, ly);
    h.y = split_hi(v.z, v.w, lz, lw);
    l.x = pack2(__float2half_rn(lx), __float2half_rn(ly));
    l.y = pack2(__float2half_rn(lz), __float2half_rn(lw));
    ((uint2*)g_xh)[c] = h;
    ((uint2*)g_xl)[c] = l;
}

// ============ conv W (q,k,v) -> fp16 hi/lo ============
__global__ __launch_bounds__(256) void convw_kernel(
    const float* __restrict__ Wq, const float* __restrict__ Wk, const float* __restrict__ Wv)
{
    const int per = HID * HID / 4;
    int c = blockIdx.x * 256 + threadIdx.x;
    int z = c / per;
    const float* W = (z == 0) ? Wq : (z == 1) ? Wk : Wv;
    float4 v = ((const float4*)W)[c - z * per];
    float lx, ly, lz, lw;
    uint2 h, l;
    h.x = split_hi(v.x, v.y, lx, ly);
    h.y = split_hi(v.z, v.w, lz, lw);
    l.x = pack2(__float2half_rn(lx), __float2half_rn(ly));
    l.y = pack2(__float2half_rn(lz), __float2half_rn(lw));
    ((uint2*)g_wh)[c] = h;
    ((uint2*)g_wl)[c] = l;
}

// ============ proj via HMMA: out = X @ W^T + b ============
// z<2 (Q,K): 1-pass (Ah*Bh). z==2 (V): 3-pass (+ Ah*Bl + Al*Bh).
#define PJ_XH 0
#define PJ_XL 16384
#define PJ_WH 32768
#define PJ_WL 40960
#define PJ_SMEM 49152

__global__ __launch_bounds__(256) void proj_mma_kernel(
    const float* __restrict__ bq, const float* __restrict__ bk, const float* __restrict__ bv)
{
    extern __shared__ char smem[];
    const uint32_t sbase = smem_to_u32(smem);
    const int otile = blockIdx.x, mtile = blockIdx.y, z = blockIdx.z;
    const float* bias = (z == 0) ? bq : (z == 1) ? bk : bv;
    const int tid = threadIdx.x, wid = tid >> 5, lane = tid & 31;
    const int m0 = wid * 16;
    const int rowA = m0 + (lane & 15);
    const int selA = lane >> 4;
    const int rowB8 = lane & 7;
    const int selB = (lane >> 3) & 1;
    const int c2 = 2 * (lane & 3);

    float fin[32];
#pragma unroll
    for (int e = 0; e < 32; e++) fin[e] = 0.f;

    for (int kc = 0; kc < HID / 64; kc++) {
        __syncthreads();
#pragma unroll
        for (int c = 0; c < 8; c++) {
            int idx = tid + 256 * c;
            int half = idx >> 10;
            int rem = idx & 1023;
            int row = rem >> 3, ch = rem & 7;
            const __half* src = (half ? g_xl : g_xh) +
                (size_t)(mtile * 128 + row) * HID + kc * 64 + ch * 8;
            *(uint4*)(smem + (half ? PJ_XL : PJ_XH) + SWZ8(row, ch)) = *(const uint4*)src;
        }
#pragma unroll
        for (int c = 0; c < 4; c++) {
            int idx = tid + 256 * c;
            int half = idx >> 9;
            int rem = idx & 511;
            int row = rem >> 3, ch = rem & 7;
            const __half* src = (half ? g_wl : g_wh) +
                ((size_t)z * HID + otile * 64 + row) * HID + kc * 64 + ch * 8;
            *(uint4*)(smem + (half ? PJ_WL : PJ_WH) + SWZ8(row, ch)) = *(const uint4*)src;
        }
        __syncthreads();

#pragma unroll
        for (int ks = 0; ks < 4; ks++) {
            uint32_t Ah[4], Al[4];
            ldsm_x4(Ah, sbase + PJ_XH + SWZ8(rowA, ks * 2 + selA));
            if (z == 2) ldsm_x4(Al, sbase + PJ_XL + SWZ8(rowA, ks * 2 + selA));
#pragma unroll
            for (int nf = 0; nf < 8; nf++) {
                uint32_t Bh[2], Bl[2];
                ldsm_x2(Bh, sbase + PJ_WH + SWZ8(nf * 8 + rowB8, ks * 2 + selB));
                mma16816(fin + nf * 4, Ah, Bh);
                if (z == 2) {
                    ldsm_x2(Bl, sbase + PJ_WL + SWZ8(nf * 8 + rowB8, ks * 2 + selB));
                    mma16816(fin + nf * 4, Ah, Bl);
                    mma16816(fin + nf * 4, Al, Bh);
                }
            }
        }
    }

    const int ma = mtile * 128 + m0 + (lane >> 2);
    const int b = ma >> 11;
    const int sa = ma & (SQ - 1), sb = sa + 8;
    const int bn = b * NH + otile;
#pragma unroll
    for (int nf = 0; nf < 8; nf++) {
        int col = nf * 8 + c2;
        float bsx = bias[otile * 64 + col], bsy = bias[otile * 64 + col + 1];
        float a0 = fin[nf * 4 + 0] + bsx, a1 = fin[nf * 4 + 1] + bsy;
        float b0 = fin[nf * 4 + 2] + bsx, b1 = fin[nf * 4 + 3] + bsy;
        size_t offa = ((size_t)bn * SQ + sa) * DH + col;
        size_t offb = ((size_t)bn * SQ + sb) * DH + col;
        if (z == 2) {
            *(float2*)&g_v[offa] = make_float2(a0, a1);
            *(float2*)&g_v[offb] = make_float2(b0, b1);
        } else {
            __half* dh = (z == 0) ? g_qh : g_kh;
            *(unsigned*)&dh[offa] = pack2(__float2half_rn(a0), __float2half_rn(a1));
            *(unsigned*)&dh[offb] = pack2(__float2half_rn(b0), __float2half_rn(b1));
        }
    }
}

// ============ qb via HMMA (fp16 1-pass): q'_r = q @ bili[r,n] -> slot 1+r ============
#define QB_QH 0
#define QB_BH 16384
#define QB_SMEM 24576

__global__ __launch_bounds__(256) void qb_mma_kernel(const float* __restrict__ bili)
{
    extern __shared__ char smem[];
    const uint32_t sbase = smem_to_u32(smem);
    const int it = blockIdx.x, bn = blockIdx.y, r = blockIdx.z;
    const int n = bn % NH;
    const int tid = threadIdx.x, wid = tid >> 5, lane = tid & 31;
    const int m0 = wid * 16;
    const int rowA = m0 + (lane & 15);
    const int selA = lane >> 4;
    const int rowB8 = lane & 7;
    const int selB = (lane >> 3) & 1;
    const int c2 = 2 * (lane & 3);

#pragma unroll
    for (int c = 0; c < 4; c++) {
        int idx = tid + 256 * c;
        int row = idx >> 3, ch = idx & 7;
        const __half* src = g_qh + ((size_t)bn * SQ + it * 128 + row) * DH + ch * 8;
        *(uint4*)(smem + QB_QH + SWZ8(row, ch)) = *(const uint4*)src;
    }
    const float* bb = bili + ((size_t)r * NH + n) * DH * DH;
#pragma unroll
    for (int c = 0; c < 16; c++) {
        int id = tid + 256 * c;
        int p = id >> 6, t = id & 63;
        float v = bb[p * 64 + t];
        uint32_t byteoff = SWZ8(t, p >> 3) + (p & 7) * 2;
        *(__half*)(smem + QB_BH + byteoff) = __float2half_rn(v);
    }
    __syncthreads();

    float fin[32];
#pragma unroll
    for (int e = 0; e < 32; e++) fin[e] = 0.f;

#pragma unroll
    for (int ks = 0; ks < 4; ks++) {
        uint32_t Ah[4];
        ldsm_x4(Ah, sbase + QB_QH + SWZ8(rowA, ks * 2 + selA));
#pragma unroll
        for (int nf = 0; nf < 8; nf++) {
            uint32_t Bh[2];
            ldsm_x2(Bh, sbase + QB_BH + SWZ8(nf * 8 + rowB8, ks * 2 + selB));
            mma16816(fin + nf * 4, Ah, Bh);
        }
    }

    const int slot = 1 + r;
    const int ia = it * 128 + m0 + (lane >> 2);
    const int ib = ia + 8;
#pragma unroll
    for (int nf = 0; nf < 8; nf++) {
        int col = nf * 8 + c2;
        size_t offa = (((size_t)slot * BN + bn) * SQ + ia) * DH + col;
        size_t offb = (((size_t)slot * BN + bn) * SQ + ib) * DH + col;
        *(unsigned*)&g_qh[offa] = pack2(__float2half_rn(fin[nf * 4 + 0]), __float2half_rn(fin[nf * 4 + 1]));
        *(unsigned*)&g_qh[offb] = pack2(__float2half_rn(fin[nf * 4 + 2]), __float2half_rn(fin[nf * 4 + 3]));
    }
}

// ============ transpose+convert V -> g_vth [bn][d][s] (fp16) ============
__global__ __launch_bounds__(256) void vt_kernel()
{
    const int st = blockIdx.x, bn = blockIdx.y;
    __shared__ float tile[64][65];
    const int t = threadIdx.x;
#pragma unroll
    for (int c = 0; c < 4; c++) {
        int id = t + 256 * c, row = id >> 4, c4 = (id & 15) << 2;
        float4 v = *(const float4*)&g_v[((size_t)bn * SQ + st * 64 + row) * DH + c4];
        tile[row][c4 + 0] = v.x; tile[row][c4 + 1] = v.y;
        tile[row][c4 + 2] = v.z; tile[row][c4 + 3] = v.w;
    }
    __syncthreads();
#pragma unroll
    for (int c = 0; c < 4; c++) {
        int id = t + 256 * c, d = id >> 4, s4 = (id & 15) << 2;
        uint2 hv;
        hv.x = pack2(__float2half_rn(tile[s4 + 0][d]), __float2half_rn(tile[s4 + 1][d]));
        hv.y = pack2(__float2half_rn(tile[s4 + 2][d]), __float2half_rn(tile[s4 + 3][d]));
        size_t off = ((size_t)bn * DH + d) * SQ + st * 64 + s4;
        *(uint2*)&g_vth[off] = hv;
    }
}

// ============ pack adj -> bitmask [r][b][jword][i] ============
__global__ __launch_bounds__(256) void pack_kernel(const float* __restrict__ adj)
{
    const int jw = blockIdx.x, b = blockIdx.y, r = blockIdx.z;
#pragma unroll
    for (int ii = 0; ii < 8; ii++) {
        int i = threadIdx.x + 256 * ii;
        const float* src = adj + (((size_t)(r * BB + b)) * SQ + i) * SQ + jw * 32;
        unsigned bits = 0;
#pragma unroll
        for (int e8 = 0; e8 < 8; e8++) {
            float4 v = *(const float4*)(src + e8 * 4);
            bits |= (unsigned)(v.x != 0.f) << (e8 * 4 + 0);
            bits |= (unsigned)(v.y != 0.f) << (e8 * 4 + 1);
            bits |= (unsigned)(v.z != 0.f) << (e8 * 4 + 2);
            bits |= (unsigned)(v.w != 0.f) << (e8 * 4 + 3);
        }
        g_adjbits[((size_t)(r * BB + b) * 64 + jw) * SQ + i] = bits;
    }
}

// ============ fused flash (fp16, cp.async pipelined) ============
// grid (NH, SQ/64, BB), block 128. SMEM 64KB.
#define FQ(s)     ((s) * 8192)              // slots 0..5
#define FKT       49152                     // K, 8KB
#define FVT       57344                     // V^T, 8KB
#define FL_SMEM   65536

__global__ __launch_bounds__(128) void flash_kernel(
    const float* __restrict__ absb, const float* __restrict__ mask,
    float* __restrict__ out)
{
    extern __shared__ char smem[];
    const uint32_t sbase = smem_to_u32(smem);
    const int n = blockIdx.x, it = blockIdx.y, b = blockIdx.z;
    const int bn = b * NH + n;
    const int i0 = it * 64;
    const int tid = threadIdx.x, wid = tid >> 5, lane = tid & 31;
    const int m0 = wid * 16;

    auto load_k = [&](int jt) {
#pragma unroll
        for (int c = 0; c < 4; c++) {
            int idx = tid + 128 * c;
            int row = idx >> 3, ch = idx & 7;
            const __half* src = g_kh + ((size_t)bn * SQ + jt * 64 + row) * DH + ch * 8;
            cpa16(sbase + FKT + SWZ8(row, ch), src);
        }
        CP_COMMIT();
    };
    auto load_v = [&](int jt) {
#pragma unroll
        for (int c = 0; c < 4; c++) {
            int idx = tid + 128 * c;
            int row = idx >> 3, ch = idx & 7;
            const __half* src = g_vth + ((size_t)bn * DH + row) * SQ + jt * 64 + ch * 8;
            cpa16(sbase + FVT + SWZ8(row, ch), src);
        }
        CP_COMMIT();
    };

    load_k(0);
    load_v(0);

    // ---- load 6 Q tiles (64x64 fp16, swizzled) ----
#pragma unroll
    for (int c = 0; c < 24; c++) {
        int idx = tid + 128 * c;
        int tile = idx >> 9;
        int rem = idx & 511;
        int row = rem >> 3, ch = rem & 7;
        const __half* src = g_qh +
            (((size_t)tile * BN + bn) * SQ + i0 + row) * DH + ch * 8;
        *(uint4*)(smem + FQ(tile) + SWZ8(row, ch)) = *(const uint4*)src;
    }

    const int rowA = m0 + (lane & 15);
    const int selA = lane >> 4;
    const int rowB8 = lane & 7;
    const int selB = (lane >> 3) & 1;
    const int c2 = 2 * (lane & 3);
    const int ia = i0 + m0 + (lane >> 2);
    const int ib = ia + 8;

    float ab[RR];
#pragma unroll
    for (int r = 0; r < RR; r++) ab[r] = absb[r * NH + n];
    const float* maskb = mask + b * SQ;

    float O[32];
#pragma unroll
    for (int e = 0; e < 32; e++) O[e] = 0.f;
    float mr[2] = {-1e30f, -1e30f};
    float lr[2] = {0.f, 0.f};

    for (int jt = 0; jt < 32; jt++) {
        CP_WAIT(1);                 // K(jt) ready
        __syncthreads();

        // ---- QK + structural bias ----
        float fin[32];
#pragma unroll
        for (int jh = 0; jh < 2; jh++) {
            uint32_t BK[4][4][2];
#pragma unroll
            for (int ks = 0; ks < 4; ks++)
#pragma unroll
                for (int nf = 0; nf < 4; nf++)
                    ldsm_x2(BK[ks][nf],
                            sbase + FKT + SWZ8(jh * 32 + nf * 8 + rowB8, ks * 2 + selB));

            const int jw = jt * 2 + jh;
            unsigned aw1[RR], aw2[RR];
#pragma unroll
            for (int r = 0; r < RR; r++) {
                aw1[r] = g_adjbits[((size_t)(r * BB + b) * 64 + jw) * SQ + ia];
                aw2[r] = g_adjbits[((size_t)(r * BB + b) * 64 + jw) * SQ + ib];
            }

            float facc[16] = {};
#pragma unroll
            for (int ks = 0; ks < 4; ks++) {
                uint32_t Ah[4];
                ldsm_x4(Ah, sbase + FQ(0) + SWZ8(rowA, ks * 2 + selA));
#pragma unroll
                for (int nf = 0; nf < 4; nf++)
                    mma16816(facc + nf * 4, Ah, BK[ks][nf]);
            }

#pragma unroll
            for (int s = 1; s < 6; s++) {
                float tmp[16] = {};
#pragma unroll
                for (int ks = 0; ks < 4; ks++) {
                    uint32_t Ah[4];
                    ldsm_x4(Ah, sbase + FQ(s) + SWZ8(rowA, ks * 2 + selA));
#pragma unroll
                    for (int nf = 0; nf < 4; nf++)
                        mma16816(tmp + nf * 4, Ah, BK[ks][nf]);
                }
                const int r = s - 1;
                const float abr = ab[r];
#pragma unroll
                for (int nf = 0; nf < 4; nf++) {
                    int sh = nf * 8 + c2;
                    if ((aw1[r] >> sh) & 1)       facc[nf * 4 + 0] += tmp[nf * 4 + 0] + abr;
                    if ((aw1[r] >> (sh + 1)) & 1) facc[nf * 4 + 1] += tmp[nf * 4 + 1] + abr;
                    if ((aw2[r] >> sh) & 1)       facc[nf * 4 + 2] += tmp[nf * 4 + 2] + abr;
                    if ((aw2[r] >> (sh + 1)) & 1) facc[nf * 4 + 3] += tmp[nf * 4 + 3] + abr;
                }
            }
#pragma unroll
            for (int e = 0; e < 16; e++) fin[jh * 16 + e] = facc[e];
        }

        __syncthreads();            // K reads done
        if (jt < 31) load_k(jt + 1);

        // ---- scale + mask ----
#pragma unroll
        for (int q = 0; q < 8; q++) {
            int jh = q >> 2, nf = q & 3;
            float2 mk = __ldg((const float2*)&maskb[jt * 64 + jh * 32 + nf * 8 + c2]);
            fin[q * 4 + 0] = fin[q * 4 + 0] * 0.125f + mk.x;
            fin[q * 4 + 1] = fin[q * 4 + 1] * 0.125f + mk.y;
            fin[q * 4 + 2] = fin[q * 4 + 2] * 0.125f + mk.x;
            fin[q * 4 + 3] = fin[q * 4 + 3] * 0.125f + mk.y;
        }

        // ---- online softmax over 64 cols ----
        float mxa = -1e30f, mxb = -1e30f;
#pragma unroll
        for (int q = 0; q < 8; q++) {
            mxa = fmaxf(mxa, fmaxf(fin[q * 4 + 0], fin[q * 4 + 1]));
            mxb = fmaxf(mxb, fmaxf(fin[q * 4 + 2], fin[q * 4 + 3]));
        }
        mxa = fmaxf(mxa, __shfl_xor_sync(0xffffffffu, mxa, 1));
        mxa = fmaxf(mxa, __shfl_xor_sync(0xffffffffu, mxa, 2));
        mxb = fmaxf(mxb, __shfl_xor_sync(0xffffffffu, mxb, 1));
        mxb = fmaxf(mxb, __shfl_xor_sync(0xffffffffu, mxb, 2));
        float mna = fmaxf(mr[0], mxa), mnb = fmaxf(mr[1], mxb);
        float ala = __expf(mr[0] - mna), alb = __expf(mr[1] - mnb);
        mr[0] = mna; mr[1] = mnb;

        float sa = 0.f, sb = 0.f;
#pragma unroll
        for (int q = 0; q < 8; q++) {
            fin[q * 4 + 0] = __expf(fin[q * 4 + 0] - mna);
            fin[q * 4 + 1] = __expf(fin[q * 4 + 1] - mna);
            fin[q * 4 + 2] = __expf(fin[q * 4 + 2] - mnb);
            fin[q * 4 + 3] = __expf(fin[q * 4 + 3] - mnb);
            sa += fin[q * 4 + 0] + fin[q * 4 + 1];
            sb += fin[q * 4 + 2] + fin[q * 4 + 3];
        }
        sa += __shfl_xor_sync(0xffffffffu, sa, 1);
        sa += __shfl_xor_sync(0xffffffffu, sa, 2);
        sb += __shfl_xor_sync(0xffffffffu, sb, 1);
        sb += __shfl_xor_sync(0xffffffffu, sb, 2);
        lr[0] = lr[0] * ala + sa;
        lr[1] = lr[1] * alb + sb;

#pragma unroll
        for (int dn = 0; dn < 8; dn++) {
            O[dn * 4 + 0] *= ala; O[dn * 4 + 1] *= ala;
            O[dn * 4 + 2] *= alb; O[dn * 4 + 3] *= alb;
        }

        // ---- pack P fp16 (hi only) ----
        uint32_t Ph[4][4];
#pragma unroll
        for (int jk = 0; jk < 4; jk++) {
            int jh = jk >> 1, jj = jk & 1;
            int b0 = jh * 16 + (2 * jj) * 4;
            int b1 = jh * 16 + (2 * jj + 1) * 4;
            Ph[jk][0] = pack2(__float2half_rn(fin[b0 + 0]), __float2half_rn(fin[b0 + 1]));
            Ph[jk][1] = pack2(__float2half_rn(fin[b0 + 2]), __float2half_rn(fin[b0 + 3]));
            Ph[jk][2] = pack2(__float2half_rn(fin[b1 + 0]), __float2half_rn(fin[b1 + 1]));
            Ph[jk][3] = pack2(__float2half_rn(fin[b1 + 2]), __float2half_rn(fin[b1 + 3]));
        }

        if (jt < 31) { CP_WAIT(1); } else { CP_WAIT(0); }   // V(jt) ready
        __syncthreads();

        // ---- P @ V (1-pass: Ph*Vh) ----
#pragma unroll
        for (int jk = 0; jk < 4; jk++) {
#pragma unroll
            for (int dn = 0; dn < 8; dn++) {
                uint32_t BVh[2];
                ldsm_x2(BVh, sbase + FVT + SWZ8(dn * 8 + rowB8, jk * 2 + selB));
                mma16816(O + dn * 4, Ph[jk], BVh);
            }
        }

        __syncthreads();            // V reads done
        if (jt < 31) load_v(jt + 1);
    }

    const float inva = 1.0f / lr[0], invb = 1.0f / lr[1];
#pragma unroll
    for (int dn = 0; dn < 8; dn++) {
        int d = dn * 8 + c2;
        float2 oa, ob;
        oa.x = O[dn * 4 + 0] * inva; oa.y = O[dn * 4 + 1] * inva;
        ob.x = O[dn * 4 + 2] * invb; ob.y = O[dn * 4 + 3] * invb;
        *(float2*)&out[((size_t)b * SQ + ia) * HID + n * 64 + d] = oa;
        *(float2*)&out[((size_t)b * SQ + ib) * HID + n * 64 + d] = ob;
    }
}

// =================================================================
extern "C" void kernel_launch(void* const* d_in, const int* in_sizes, int n_in,
                              void* d_out, int out_size)
{
    const float* hidden = (const float*)d_in[0];
    const float* mask   = (const float*)d_in[1];
    const float* adj    = (const float*)d_in[2];
    const float* Wq     = (const float*)d_in[3];
    const float* bq     = (const float*)d_in[4];
    const float* Wk     = (const float*)d_in[5];
    const float* bk     = (const float*)d_in[6];
    const float* Wv     = (const float*)d_in[7];
    const float* bv     = (const float*)d_in[8];
    const float* bili   = (const float*)d_in[9];
    const float* absb   = (const float*)d_in[10];
    float* out = (float*)d_out;
    (void)in_sizes; (void)n_in; (void)out_size;

    cudaFuncSetAttribute(proj_mma_kernel, cudaFuncAttributeMaxDynamicSharedMemorySize, PJ_SMEM);
    cudaFuncSetAttribute(qb_mma_kernel, cudaFuncAttributeMaxDynamicSharedMemorySize, QB_SMEM);
    cudaFuncSetAttribute(flash_kernel, cudaFuncAttributeMaxDynamicSharedMemorySize, FL_SMEM);

    convx_kernel<<<BB * SQ * HID / 4 / 256, 256>>>(hidden);
    convw_kernel<<<3 * HID * HID / 4 / 256, 256>>>(Wq, Wk, Wv);
    proj_mma_kernel<<<dim3(HID / 64, BB * SQ / 128, 3), 256, PJ_SMEM>>>(bq, bk, bv);
    qb_mma_kernel<<<dim3(SQ / 128, BN, RR), 256, QB_SMEM>>>(bili);
    vt_kernel<<<dim3(SQ / 64, BN), 256>>>();
    pack_kernel<<<dim3(SQ / 32, BB, RR), 256>>>(adj);
    flash_kernel<<<dim3(NH, SQ / 64, BB), 128, FL_SMEM>>>(absb, mask, out);
}